// round 3
// baseline (speedup 1.0000x reference)
#include <cuda_runtime.h>

#define BATCH 8
#define CH    256
#define HW    16384   // 128*128
#define TOK   128
#define HEADS 8
#define DH    64
#define INNER 512
#define NFEAT 8192    // 128*64
#define SPAD  132
#define VP    132     // Vs row stride (floats)

// ---- scratch (device globals; no runtime allocation) ----
__device__ float g_qkv [(size_t)3*BATCH*INNER*HW]; // [kind][b][o][hw], o=head*64+d
__device__ float g_bufH[(size_t)BATCH*INNER*HW];   // row-attn output  [b][o][hw]
__device__ float g_bufW[(size_t)BATCH*INNER*HW];   // col-attn output  [b][o][hw]

// packed f32x2 FMA (sm_100+): 2 FMA per issue slot
__device__ __forceinline__ float2 ffma2(float2 c, float2 a, float2 b) {
    unsigned long long cu = *reinterpret_cast<unsigned long long*>(&c);
    unsigned long long au = *reinterpret_cast<unsigned long long*>(&a);
    unsigned long long bu = *reinterpret_cast<unsigned long long*>(&b);
    asm("fma.rn.f32x2 %0, %1, %2, %0;" : "+l"(cu) : "l"(au), "l"(bu));
    float2 r;
    *reinterpret_cast<unsigned long long*>(&r) = cu;
    return r;
}

__device__ __forceinline__ void mma8x8(float2 (&acc)[8][4], const float (&a8)[8], const float (&b8)[8]) {
    float2 bv[4];
    #pragma unroll
    for (int j = 0; j < 4; j++) bv[j] = make_float2(b8[2*j], b8[2*j+1]);
    #pragma unroll
    for (int i = 0; i < 8; i++) {
        float2 av = make_float2(a8[i], a8[i]);
        #pragma unroll
        for (int j = 0; j < 4; j++) acc[i][j] = ffma2(acc[i][j], av, bv[j]);
    }
}

// ============================================================
// K1: qkv = w_qkv @ x   (per batch: [1536x256] @ [256x16384])
// writes q/k/v into g_qkv [kind][b][o%512][hw]
// ============================================================
__global__ void __launch_bounds__(256) qkv_gemm_kernel(
    const float* __restrict__ x, const float* __restrict__ wqkv)
{
    __shared__ float As[16][128];
    __shared__ float Bs[16][128];
    const int b  = blockIdx.z;
    const int m0 = blockIdx.y * 128;
    const int n0 = blockIdx.x * 128;
    const int tid = threadIdx.x;
    const int tm = tid >> 4, tn = tid & 15;
    const float* __restrict__ xb = x + (size_t)b * CH * HW;

    float2 acc[8][4];
    #pragma unroll
    for (int i = 0; i < 8; i++)
        #pragma unroll
        for (int j = 0; j < 4; j++) acc[i][j] = make_float2(0.f, 0.f);

    for (int k0 = 0; k0 < CH; k0 += 16) {
        { // A tile: wqkv[m0+m][k0+c], stored transposed As[c][m]
            int r = tid >> 2;
            int c = (tid & 3) << 2;
            #pragma unroll
            for (int rr = 0; rr < 2; rr++) {
                int m = r + rr * 64;
                float4 v = *reinterpret_cast<const float4*>(&wqkv[(size_t)(m0 + m) * CH + k0 + c]);
                As[c+0][m] = v.x; As[c+1][m] = v.y; As[c+2][m] = v.z; As[c+3][m] = v.w;
            }
        }
        { // B tile: x[b][k0+k][n0+c]
            int r = tid >> 5;
            int c = (tid & 31) << 2;
            #pragma unroll
            for (int rr = 0; rr < 2; rr++) {
                int k = r + rr * 8;
                *reinterpret_cast<float4*>(&Bs[k][c]) =
                    *reinterpret_cast<const float4*>(&xb[(size_t)(k0 + k) * HW + n0 + c]);
            }
        }
        __syncthreads();
        #pragma unroll
        for (int k = 0; k < 16; k++) {
            float a8[8], b8[8];
            *reinterpret_cast<float4*>(a8)     = *reinterpret_cast<const float4*>(&As[k][tm*8]);
            *reinterpret_cast<float4*>(a8 + 4) = *reinterpret_cast<const float4*>(&As[k][tm*8 + 4]);
            *reinterpret_cast<float4*>(b8)     = *reinterpret_cast<const float4*>(&Bs[k][tn*8]);
            *reinterpret_cast<float4*>(b8 + 4) = *reinterpret_cast<const float4*>(&Bs[k][tn*8 + 4]);
            mma8x8(acc, a8, b8);
        }
        __syncthreads();
    }

    #pragma unroll
    for (int i = 0; i < 8; i++) {
        int o = m0 + tm * 8 + i;
        int kind = o >> 9, oo = o & 511;
        float* dst = g_qkv + (((size_t)kind * BATCH + b) * INNER + oo) * HW + n0 + tn * 8;
        float4 v0 = make_float4(acc[i][0].x, acc[i][0].y, acc[i][1].x, acc[i][1].y);
        float4 v1 = make_float4(acc[i][2].x, acc[i][2].y, acc[i][3].x, acc[i][3].y);
        *reinterpret_cast<float4*>(dst)     = v0;
        *reinterpret_cast<float4*>(dst + 4) = v1;
    }
}

// ============================================================
// K2: axial attention. grid (64 = b*head, 2 = mode row/col)
// mode 0: tokens = rows (h), features = (d,w)  -> g_bufH
// mode 1: tokens = cols (w), features = (d,h)  -> g_bufW
// ============================================================
extern __shared__ float attn_smem[];

__global__ void __launch_bounds__(256) attn_kernel()
{
    float* Ssm  = attn_smem;            // [j][i] : 128*128
    float* sbuf = attn_smem + TOK * TOK;

    const int tid  = threadIdx.x;
    const int tm   = tid >> 4, tn = tid & 15;
    const int bh   = blockIdx.x;
    const int mode = blockIdx.y;
    const int b    = bh >> 3, head = bh & 7;

    const size_t base = ((size_t)b * INNER + head * DH) * HW;
    const float* __restrict__ qb = g_qkv + base;
    const float* __restrict__ kb = g_qkv + (size_t)BATCH * INNER * HW + base;
    const float* __restrict__ vb = g_qkv + (size_t)2 * BATCH * INNER * HW + base;

    // ---------------- phase 1: S = Q K^T ----------------
    float* Qs = sbuf;              // [16][SPAD], [k][token]
    float* Ks = sbuf + 16 * SPAD;

    float2 acc[8][4];
    #pragma unroll
    for (int i = 0; i < 8; i++)
        #pragma unroll
        for (int j = 0; j < 4; j++) acc[i][j] = make_float2(0.f, 0.f);

    for (int c = 0; c < NFEAT / 16; c++) {   // 512 chunks of 16 features
        int d   = c >> 3;
        int off = (c & 7) << 4;  // w0 (row) or h0 (col)
        if (mode == 0) {
            // addr(token i, k) = qb[d*HW + i*128 + off + k]
            int r  = tid >> 1;
            int hf = (tid & 1) * 8;
            const float* qs = qb + (size_t)d * HW + r * TOK + off + hf;
            const float* ks = kb + (size_t)d * HW + r * TOK + off + hf;
            float4 q0 = *reinterpret_cast<const float4*>(qs);
            float4 q1 = *reinterpret_cast<const float4*>(qs + 4);
            float4 k0 = *reinterpret_cast<const float4*>(ks);
            float4 k1 = *reinterpret_cast<const float4*>(ks + 4);
            Qs[(hf+0)*SPAD + r] = q0.x; Qs[(hf+1)*SPAD + r] = q0.y;
            Qs[(hf+2)*SPAD + r] = q0.z; Qs[(hf+3)*SPAD + r] = q0.w;
            Qs[(hf+4)*SPAD + r] = q1.x; Qs[(hf+5)*SPAD + r] = q1.y;
            Qs[(hf+6)*SPAD + r] = q1.z; Qs[(hf+7)*SPAD + r] = q1.w;
            Ks[(hf+0)*SPAD + r] = k0.x; Ks[(hf+1)*SPAD + r] = k0.y;
            Ks[(hf+2)*SPAD + r] = k0.z; Ks[(hf+3)*SPAD + r] = k0.w;
            Ks[(hf+4)*SPAD + r] = k1.x; Ks[(hf+5)*SPAD + r] = k1.y;
            Ks[(hf+6)*SPAD + r] = k1.z; Ks[(hf+7)*SPAD + r] = k1.w;
        } else {
            // addr(token j, k) = qb[d*HW + (off+k)*128 + j]
            #pragma unroll
            for (int it = 0; it < 2; it++) {
                int idx = tid + it * 256;
                int kk  = idx >> 5;
                int j4  = (idx & 31) << 2;
                *reinterpret_cast<float4*>(&Qs[kk*SPAD + j4]) =
                    *reinterpret_cast<const float4*>(&qb[(size_t)d*HW + (off+kk)*TOK + j4]);
                *reinterpret_cast<float4*>(&Ks[kk*SPAD + j4]) =
                    *reinterpret_cast<const float4*>(&kb[(size_t)d*HW + (off+kk)*TOK + j4]);
            }
        }
        __syncthreads();
        #pragma unroll
        for (int k = 0; k < 16; k++) {
            float a8[8], b8[8];
            *reinterpret_cast<float4*>(a8)     = *reinterpret_cast<const float4*>(&Qs[k*SPAD + tm*8]);
            *reinterpret_cast<float4*>(a8 + 4) = *reinterpret_cast<const float4*>(&Qs[k*SPAD + tm*8 + 4]);
            *reinterpret_cast<float4*>(b8)     = *reinterpret_cast<const float4*>(&Ks[k*SPAD + tn*8]);
            *reinterpret_cast<float4*>(b8 + 4) = *reinterpret_cast<const float4*>(&Ks[k*SPAD + tn*8 + 4]);
            mma8x8(acc, a8, b8);
        }
        __syncthreads();
    }

    // store raw logits S[j][i]
    #pragma unroll
    for (int i = 0; i < 8; i++) {
        #pragma unroll
        for (int j = 0; j < 4; j++) {
            Ssm[(tn*8 + 2*j    ) * TOK + tm*8 + i] = acc[i][j].x;
            Ssm[(tn*8 + 2*j + 1) * TOK + tm*8 + i] = acc[i][j].y;
        }
    }
    __syncthreads();

    // ---------------- softmax over j (per output token i) ----------------
    if (tid < TOK) {
        const int i = tid;
        float mx = -1e30f;
        for (int j = 0; j < TOK; j++) mx = fmaxf(mx, Ssm[j*TOK + i]);
        float s = 0.f;
        for (int j = 0; j < TOK; j++) {
            float e = __expf((Ssm[j*TOK + i] - mx) * 0.125f);
            s += e;
            Ssm[j*TOK + i] = e;
        }
        float inv = 1.f / s;
        for (int j = 0; j < TOK; j++) Ssm[j*TOK + i] *= inv;
    }
    __syncthreads();

    // ---------------- phase 2: O = P V ----------------
    // Per chunk: one full d-plane (128 tokens x 128 features). Both modes load
    // the identical plane copy Vs[r][c] = vb[d*HW + r*128 + c].
    float* Vs = sbuf;  // [128][VP]
    float* outbuf = (mode == 0) ? g_bufH : g_bufW;
    float* dbase0 = outbuf + ((size_t)b * INNER + head * DH) * HW;

    for (int d = 0; d < DH; d++) {
        #pragma unroll
        for (int it = 0; it < 16; it++) {
            int idx = tid + it * 256;     // 4096 float4 slots
            int r  = idx >> 5;
            int c4 = (idx & 31) << 2;
            *reinterpret_cast<float4*>(&Vs[r*VP + c4]) =
                *reinterpret_cast<const float4*>(&vb[(size_t)d*HW + r*TOK + c4]);
        }
        __syncthreads();

        float2 oacc[8][4];
        #pragma unroll
        for (int i = 0; i < 8; i++)
            #pragma unroll
            for (int j = 0; j < 4; j++) oacc[i][j] = make_float2(0.f, 0.f);

        if (mode == 0) {
            // O[i=row_token][w] = sum_j P[j][i] * Vs[j][w]
            #pragma unroll 4
            for (int k = 0; k < TOK; k++) {
                float a8[8], b8[8];
                *reinterpret_cast<float4*>(a8)     = *reinterpret_cast<const float4*>(&Ssm[k*TOK + tm*8]);
                *reinterpret_cast<float4*>(a8 + 4) = *reinterpret_cast<const float4*>(&Ssm[k*TOK + tm*8 + 4]);
                *reinterpret_cast<float4*>(b8)     = *reinterpret_cast<const float4*>(&Vs[k*VP + tn*8]);
                *reinterpret_cast<float4*>(b8 + 4) = *reinterpret_cast<const float4*>(&Vs[k*VP + tn*8 + 4]);
                mma8x8(oacc, a8, b8);
            }
            // store: bufH[d][tok][w]
            float* dstb = dbase0 + (size_t)d * HW;
            #pragma unroll
            for (int i = 0; i < 8; i++) {
                int tok = tm * 8 + i;
                float* dst = dstb + (size_t)tok * TOK + tn * 8;
                float4 v0 = make_float4(oacc[i][0].x, oacc[i][0].y, oacc[i][1].x, oacc[i][1].y);
                float4 v1 = make_float4(oacc[i][2].x, oacc[i][2].y, oacc[i][3].x, oacc[i][3].y);
                *reinterpret_cast<float4*>(dst)     = v0;
                *reinterpret_cast<float4*>(dst + 4) = v1;
            }
        } else {
            // Ot[h][w_token] = sum_j Vs[h][j]... careful: V_w[token j][(d,h)] = vb[d*HW + h*128 + j] = Vs[h][j]
            // Ot[h][i] = sum_j Vs[h][j] * P[j][i]
            #pragma unroll 4
            for (int k = 0; k < TOK; k++) {    // k = token j
                float a8[8], b8[8];
                #pragma unroll
                for (int t = 0; t < 8; t++) a8[t] = Vs[(tm*8 + t)*VP + k];
                *reinterpret_cast<float4*>(b8)     = *reinterpret_cast<const float4*>(&Ssm[k*TOK + tn*8]);
                *reinterpret_cast<float4*>(b8 + 4) = *reinterpret_cast<const float4*>(&Ssm[k*TOK + tn*8 + 4]);
                mma8x8(oacc, a8, b8);
            }
            // store: bufW[d][h][w] with h = tm*8+i, w = tn*8+..
            float* dstb = dbase0 + (size_t)d * HW;
            #pragma unroll
            for (int i = 0; i < 8; i++) {
                int hloc = tm * 8 + i;
                float* dst = dstb + (size_t)hloc * TOK + tn * 8;
                float4 v0 = make_float4(oacc[i][0].x, oacc[i][0].y, oacc[i][1].x, oacc[i][1].y);
                float4 v1 = make_float4(oacc[i][2].x, oacc[i][2].y, oacc[i][3].x, oacc[i][3].y);
                *reinterpret_cast<float4*>(dst)     = v0;
                *reinterpret_cast<float4*>(dst + 4) = v1;
            }
        }
        __syncthreads();
    }
}

// ============================================================
// K3: out = w_out @ (0.5*(bufH+bufW)) + b_out + x
// ============================================================
__global__ void __launch_bounds__(256) out_conv_kernel(
    const float* __restrict__ x, const float* __restrict__ wout,
    const float* __restrict__ bout, float* __restrict__ out)
{
    __shared__ float As[16][128];
    __shared__ float Bs[16][128];
    const int b  = blockIdx.z;
    const int m0 = blockIdx.y * 128;
    const int n0 = blockIdx.x * 128;
    const int tid = threadIdx.x;
    const int tm = tid >> 4, tn = tid & 15;

    float2 acc[8][4];
    #pragma unroll
    for (int i = 0; i < 8; i++)
        #pragma unroll
        for (int j = 0; j < 4; j++) acc[i][j] = make_float2(0.f, 0.f);

    for (int k0 = 0; k0 < INNER; k0 += 16) {
        {
            int r = tid >> 2;
            int c = (tid & 3) << 2;
            #pragma unroll
            for (int rr = 0; rr < 2; rr++) {
                int m = r + rr * 64;
                float4 v = *reinterpret_cast<const float4*>(&wout[(size_t)(m0 + m) * INNER + k0 + c]);
                As[c+0][m] = v.x; As[c+1][m] = v.y; As[c+2][m] = v.z; As[c+3][m] = v.w;
            }
        }
        {
            int r = tid >> 5;
            int c = (tid & 31) << 2;
            #pragma unroll
            for (int rr = 0; rr < 2; rr++) {
                int k = r + rr * 8;
                size_t idx = ((size_t)b * INNER + k0 + k) * HW + n0 + c;
                float4 hv = *reinterpret_cast<const float4*>(&g_bufH[idx]);
                float4 wv = *reinterpret_cast<const float4*>(&g_bufW[idx]);
                Bs[k][c+0] = 0.5f * (hv.x + wv.x);
                Bs[k][c+1] = 0.5f * (hv.y + wv.y);
                Bs[k][c+2] = 0.5f * (hv.z + wv.z);
                Bs[k][c+3] = 0.5f * (hv.w + wv.w);
            }
        }
        __syncthreads();
        #pragma unroll
        for (int k = 0; k < 16; k++) {
            float a8[8], b8[8];
            *reinterpret_cast<float4*>(a8)     = *reinterpret_cast<const float4*>(&As[k][tm*8]);
            *reinterpret_cast<float4*>(a8 + 4) = *reinterpret_cast<const float4*>(&As[k][tm*8 + 4]);
            *reinterpret_cast<float4*>(b8)     = *reinterpret_cast<const float4*>(&Bs[k][tn*8]);
            *reinterpret_cast<float4*>(b8 + 4) = *reinterpret_cast<const float4*>(&Bs[k][tn*8 + 4]);
            mma8x8(acc, a8, b8);
        }
        __syncthreads();
    }

    #pragma unroll
    for (int i = 0; i < 8; i++) {
        int o = m0 + tm * 8 + i;
        float bias = bout[o];
        size_t ofs = ((size_t)b * CH + o) * HW + n0 + tn * 8;
        float4 x0 = *reinterpret_cast<const float4*>(&x[ofs]);
        float4 x1 = *reinterpret_cast<const float4*>(&x[ofs + 4]);
        float4 r0 = make_float4(acc[i][0].x + bias + x0.x, acc[i][0].y + bias + x0.y,
                                acc[i][1].x + bias + x0.z, acc[i][1].y + bias + x0.w);
        float4 r1 = make_float4(acc[i][2].x + bias + x1.x, acc[i][2].y + bias + x1.y,
                                acc[i][3].x + bias + x1.z, acc[i][3].y + bias + x1.w);
        *reinterpret_cast<float4*>(&out[ofs])     = r0;
        *reinterpret_cast<float4*>(&out[ofs + 4]) = r1;
    }
}

// ============================================================
extern "C" void kernel_launch(void* const* d_in, const int* in_sizes, int n_in,
                              void* d_out, int out_size) {
    (void)in_sizes; (void)n_in; (void)out_size;
    const float* x    = (const float*)d_in[0];
    const float* wqkv = (const float*)d_in[1];
    const float* wout = (const float*)d_in[2];
    const float* bout = (const float*)d_in[3];
    float* out = (float*)d_out;

    const int attn_smem = (TOK * TOK + TOK * VP) * 4;  // 133120 bytes
    cudaFuncSetAttribute(attn_kernel, cudaFuncAttributeMaxDynamicSharedMemorySize, attn_smem);

    qkv_gemm_kernel<<<dim3(HW / 128, 1536 / 128, BATCH), 256>>>(x, wqkv);
    attn_kernel<<<dim3(BATCH * HEADS, 2), 256, attn_smem>>>();
    out_conv_kernel<<<dim3(HW / 128, 2, BATCH), 256>>>(x, wout, bout, out);
}

// round 5
// speedup vs baseline: 1.3717x; 1.3717x over previous
#include <cuda_runtime.h>
#include <cuda_bf16.h>
#include <cstdint>

#define BATCH 8
#define CH    256
#define HW    16384   // 128*128
#define TOK   128
#define HEADS 8
#define DH    64
#define INNER 512
#define NFEAT 8192    // 128*64
#define SPAD  132
#define VP    132     // Vs row stride (floats)

// ---- scratch (device globals; no runtime allocation) ----
__device__ float g_qkv [(size_t)3*BATCH*INNER*HW]; // [kind][b][o][hw], o=head*64+d
__device__ float g_bufH[(size_t)BATCH*INNER*HW];   // row-attn output  [b][o][hw]
__device__ float g_bufW[(size_t)BATCH*INNER*HW];   // col-attn output  [b][o][hw]
// bf16 split operands
__device__ __nv_bfloat16 g_w_hi[(size_t)3*INNER*CH];
__device__ __nv_bfloat16 g_w_lo[(size_t)3*INNER*CH];
__device__ __nv_bfloat16 g_wo_hi[(size_t)CH*INNER];
__device__ __nv_bfloat16 g_wo_lo[(size_t)CH*INNER];
__device__ __nv_bfloat16 g_xt_hi[(size_t)BATCH*HW*CH];  // [b][hw][c]
__device__ __nv_bfloat16 g_xt_lo[(size_t)BATCH*HW*CH];

// ============================================================
// helpers
// ============================================================
__device__ __forceinline__ uint32_t smem_u32(const void* p) {
    uint32_t a;
    asm("{ .reg .u64 t; cvta.to.shared.u64 t, %1; cvt.u32.u64 %0, t; }" : "=r"(a) : "l"(p));
    return a;
}
__device__ __forceinline__ void ldsm4(uint32_t a, uint32_t& r0, uint32_t& r1, uint32_t& r2, uint32_t& r3) {
    asm volatile("ldmatrix.sync.aligned.m8n8.x4.shared.b16 {%0,%1,%2,%3}, [%4];"
                 : "=r"(r0),"=r"(r1),"=r"(r2),"=r"(r3) : "r"(a));
}
__device__ __forceinline__ void ldsm4t(uint32_t a, uint32_t& r0, uint32_t& r1, uint32_t& r2, uint32_t& r3) {
    asm volatile("ldmatrix.sync.aligned.m8n8.x4.trans.shared.b16 {%0,%1,%2,%3}, [%4];"
                 : "=r"(r0),"=r"(r1),"=r"(r2),"=r"(r3) : "r"(a));
}
__device__ __forceinline__ void mma16816(float* d, const uint32_t* a, const uint32_t* b) {
    asm volatile("mma.sync.aligned.m16n8k16.row.col.f32.bf16.bf16.f32 "
                 "{%0,%1,%2,%3}, {%4,%5,%6,%7}, {%8,%9}, {%0,%1,%2,%3};"
                 : "+f"(d[0]),"+f"(d[1]),"+f"(d[2]),"+f"(d[3])
                 : "r"(a[0]),"r"(a[1]),"r"(a[2]),"r"(a[3]), "r"(b[0]),"r"(b[1]));
}

// packed f32x2 FMA (sm_100+) for the SIMT attention kernel
__device__ __forceinline__ float2 ffma2(float2 c, float2 a, float2 b) {
    unsigned long long cu = *reinterpret_cast<unsigned long long*>(&c);
    unsigned long long au = *reinterpret_cast<unsigned long long*>(&a);
    unsigned long long bu = *reinterpret_cast<unsigned long long*>(&b);
    asm("fma.rn.f32x2 %0, %1, %2, %0;" : "+l"(cu) : "l"(au), "l"(bu));
    float2 r;
    *reinterpret_cast<unsigned long long*>(&r) = cu;
    return r;
}
__device__ __forceinline__ void mma8x8(float2 (&acc)[8][4], const float (&a8)[8], const float (&b8)[8]) {
    float2 bv[4];
    #pragma unroll
    for (int j = 0; j < 4; j++) bv[j] = make_float2(b8[2*j], b8[2*j+1]);
    #pragma unroll
    for (int i = 0; i < 8; i++) {
        float2 av = make_float2(a8[i], a8[i]);
        #pragma unroll
        for (int j = 0; j < 4; j++) acc[i][j] = ffma2(acc[i][j], av, bv[j]);
    }
}

// ============================================================
// K0a: split w_qkv and w_out into bf16 hi/lo
// ============================================================
#define NWQKV (3*INNER*CH)   // 393216
#define NWOUT (CH*INNER)     // 131072
__global__ void __launch_bounds__(256) convert_w_kernel(
    const float* __restrict__ wqkv, const float* __restrict__ wout)
{
    int i = blockIdx.x * 256 + threadIdx.x;
    if (i < NWQKV) {
        float v = wqkv[i];
        __nv_bfloat16 hi = __float2bfloat16(v);
        g_w_hi[i] = hi;
        g_w_lo[i] = __float2bfloat16(v - __bfloat162float(hi));
    } else {
        int j = i - NWQKV;
        float v = wout[j];
        __nv_bfloat16 hi = __float2bfloat16(v);
        g_wo_hi[j] = hi;
        g_wo_lo[j] = __float2bfloat16(v - __bfloat162float(hi));
    }
}

// ============================================================
// K0b: transpose x [b][c][hw] -> xt [b][hw][c], split bf16 hi/lo
// ============================================================
__global__ void __launch_bounds__(256) transpose_x_kernel(const float* __restrict__ x) {
    __shared__ float ts[32][33];
    const int b = blockIdx.z, c0 = blockIdx.y * 32, hw0 = blockIdx.x * 32;
    const int tx = threadIdx.x & 31, ty = threadIdx.x >> 5;
    const float* xb = x + ((size_t)b * CH + c0) * HW + hw0;
    #pragma unroll
    for (int i = 0; i < 4; i++) {
        int c = ty + i * 8;
        ts[c][tx] = xb[(size_t)c * HW + tx];
    }
    __syncthreads();
    size_t ob = ((size_t)b * HW + hw0) * CH + c0;
    #pragma unroll
    for (int i = 0; i < 4; i++) {
        int r = ty + i * 8;
        float v = ts[tx][r];
        __nv_bfloat16 hi = __float2bfloat16(v);
        g_xt_hi[ob + (size_t)r * CH + tx] = hi;
        g_xt_lo[ob + (size_t)r * CH + tx] = __float2bfloat16(v - __bfloat162float(hi));
    }
}

// ============================================================
// K1: qkv = w_qkv @ x via mma.sync bf16 3-pass split
// CTA 128x128, 8 warps (2m x 4n), warp tile 64x32, K=256 in 4 slabs of 64.
// ============================================================
#define K1P 72   // smem row stride in bf16 (64 + 8)

extern __shared__ __nv_bfloat16 k1_sm[];

__global__ void __launch_bounds__(256) qkv_mma_kernel() {
    __nv_bfloat16* As = k1_sm;                 // [2 split][128][K1P]
    __nv_bfloat16* Bs = k1_sm + 2 * 128 * K1P; // [2 split][128][K1P]

    const int tid = threadIdx.x;
    const int lane = tid & 31, warp = tid >> 5;
    const int wm = warp >> 2, wn = warp & 3;
    const int n0 = blockIdx.x * 128;
    const int m0 = blockIdx.y * 128;
    const int b  = blockIdx.z;

    float acc[4][4][4];
    #pragma unroll
    for (int i = 0; i < 4; i++)
        #pragma unroll
        for (int j = 0; j < 4; j++)
            #pragma unroll
            for (int q = 0; q < 4; q++) acc[i][j][q] = 0.f;

    for (int s = 0; s < 4; s++) {
        const int k0 = s * 64;
        #pragma unroll
        for (int sp = 0; sp < 2; sp++) {
            const __nv_bfloat16* src = sp ? g_w_lo : g_w_hi;
            __nv_bfloat16* dst = As + sp * 128 * K1P;
            #pragma unroll
            for (int it = 0; it < 4; it++) {
                int idx = tid + it * 256;
                int r = idx >> 3, c = (idx & 7) * 8;
                *reinterpret_cast<uint4*>(dst + r * K1P + c) =
                    *reinterpret_cast<const uint4*>(src + (size_t)(m0 + r) * CH + k0 + c);
            }
        }
        #pragma unroll
        for (int sp = 0; sp < 2; sp++) {
            const __nv_bfloat16* src = sp ? g_xt_lo : g_xt_hi;
            __nv_bfloat16* dst = Bs + sp * 128 * K1P;
            #pragma unroll
            for (int it = 0; it < 4; it++) {
                int idx = tid + it * 256;
                int r = idx >> 3, c = (idx & 7) * 8;
                *reinterpret_cast<uint4*>(dst + r * K1P + c) =
                    *reinterpret_cast<const uint4*>(src + ((size_t)b * HW + n0 + r) * CH + k0 + c);
            }
        }
        __syncthreads();

        #pragma unroll
        for (int p = 0; p < 3; p++) {   // (hi,hi) (hi,lo) (lo,hi)
            const __nv_bfloat16* Ab = As + (p == 2 ? 128 * K1P : 0);
            const __nv_bfloat16* Bb = Bs + (p == 1 ? 128 * K1P : 0);
            #pragma unroll
            for (int ks = 0; ks < 4; ks++) {
                const int kk = ks * 16;
                uint32_t af[4][4], bf2[4][2];
                #pragma unroll
                for (int mt = 0; mt < 4; mt++) {
                    uint32_t a = smem_u32(Ab + (wm * 64 + mt * 16 + (lane & 15)) * K1P + kk + (lane >> 4) * 8);
                    ldsm4(a, af[mt][0], af[mt][1], af[mt][2], af[mt][3]);
                }
                #pragma unroll
                for (int np = 0; np < 2; np++) {
                    int nrow = wn * 32 + np * 16 + (lane & 7) + ((lane >> 4) & 1) * 8;
                    int kcol = kk + ((lane >> 3) & 1) * 8;
                    uint32_t a = smem_u32(Bb + nrow * K1P + kcol);
                    ldsm4(a, bf2[np*2][0], bf2[np*2][1], bf2[np*2+1][0], bf2[np*2+1][1]);
                }
                #pragma unroll
                for (int mt = 0; mt < 4; mt++)
                    #pragma unroll
                    for (int nt = 0; nt < 4; nt++)
                        mma16816(acc[mt][nt], af[mt], bf2[nt]);
            }
        }
        __syncthreads();
    }

    // epilogue -> g_qkv[kind][b][o][hw]
    const int g = lane >> 2, tig = lane & 3;
    #pragma unroll
    for (int mt = 0; mt < 4; mt++) {
        int mbase = m0 + wm * 64 + mt * 16;
        #pragma unroll
        for (int half = 0; half < 2; half++) {
            int m = mbase + g + half * 8;
            int kind = m >> 9, oo = m & 511;
            float* rowp = g_qkv + (((size_t)kind * BATCH + b) * INNER + oo) * HW + n0;
            #pragma unroll
            for (int nt = 0; nt < 4; nt++) {
                int col = wn * 32 + nt * 8 + tig * 2;
                *reinterpret_cast<float2*>(rowp + col) =
                    make_float2(acc[mt][nt][half*2], acc[mt][nt][half*2+1]);
            }
        }
    }
}

// ============================================================
// K2: axial attention (SIMT fp32, unchanged from R3-pass)
// ============================================================
extern __shared__ float attn_smem[];

__global__ void __launch_bounds__(256) attn_kernel()
{
    float* Ssm  = attn_smem;            // [j][i] : 128*128
    float* sbuf = attn_smem + TOK * TOK;

    const int tid  = threadIdx.x;
    const int tm   = tid >> 4, tn = tid & 15;
    const int bh   = blockIdx.x;
    const int mode = blockIdx.y;
    const int b    = bh >> 3, head = bh & 7;

    const size_t base = ((size_t)b * INNER + head * DH) * HW;
    const float* __restrict__ qb = g_qkv + base;
    const float* __restrict__ kb = g_qkv + (size_t)BATCH * INNER * HW + base;
    const float* __restrict__ vb = g_qkv + (size_t)2 * BATCH * INNER * HW + base;

    float* Qs = sbuf;              // [16][SPAD], [k][token]
    float* Ks = sbuf + 16 * SPAD;

    float2 acc[8][4];
    #pragma unroll
    for (int i = 0; i < 8; i++)
        #pragma unroll
        for (int j = 0; j < 4; j++) acc[i][j] = make_float2(0.f, 0.f);

    for (int c = 0; c < NFEAT / 16; c++) {
        int d   = c >> 3;
        int off = (c & 7) << 4;
        if (mode == 0) {
            int r  = tid >> 1;
            int hf = (tid & 1) * 8;
            const float* qs = qb + (size_t)d * HW + r * TOK + off + hf;
            const float* ks = kb + (size_t)d * HW + r * TOK + off + hf;
            float4 q0 = *reinterpret_cast<const float4*>(qs);
            float4 q1 = *reinterpret_cast<const float4*>(qs + 4);
            float4 k0 = *reinterpret_cast<const float4*>(ks);
            float4 k1 = *reinterpret_cast<const float4*>(ks + 4);
            Qs[(hf+0)*SPAD + r] = q0.x; Qs[(hf+1)*SPAD + r] = q0.y;
            Qs[(hf+2)*SPAD + r] = q0.z; Qs[(hf+3)*SPAD + r] = q0.w;
            Qs[(hf+4)*SPAD + r] = q1.x; Qs[(hf+5)*SPAD + r] = q1.y;
            Qs[(hf+6)*SPAD + r] = q1.z; Qs[(hf+7)*SPAD + r] = q1.w;
            Ks[(hf+0)*SPAD + r] = k0.x; Ks[(hf+1)*SPAD + r] = k0.y;
            Ks[(hf+2)*SPAD + r] = k0.z; Ks[(hf+3)*SPAD + r] = k0.w;
            Ks[(hf+4)*SPAD + r] = k1.x; Ks[(hf+5)*SPAD + r] = k1.y;
            Ks[(hf+6)*SPAD + r] = k1.z; Ks[(hf+7)*SPAD + r] = k1.w;
        } else {
            #pragma unroll
            for (int it = 0; it < 2; it++) {
                int idx = tid + it * 256;
                int kk  = idx >> 5;
                int j4  = (idx & 31) << 2;
                *reinterpret_cast<float4*>(&Qs[kk*SPAD + j4]) =
                    *reinterpret_cast<const float4*>(&qb[(size_t)d*HW + (off+kk)*TOK + j4]);
                *reinterpret_cast<float4*>(&Ks[kk*SPAD + j4]) =
                    *reinterpret_cast<const float4*>(&kb[(size_t)d*HW + (off+kk)*TOK + j4]);
            }
        }
        __syncthreads();
        #pragma unroll
        for (int k = 0; k < 16; k++) {
            float a8[8], b8[8];
            *reinterpret_cast<float4*>(a8)     = *reinterpret_cast<const float4*>(&Qs[k*SPAD + tm*8]);
            *reinterpret_cast<float4*>(a8 + 4) = *reinterpret_cast<const float4*>(&Qs[k*SPAD + tm*8 + 4]);
            *reinterpret_cast<float4*>(b8)     = *reinterpret_cast<const float4*>(&Ks[k*SPAD + tn*8]);
            *reinterpret_cast<float4*>(b8 + 4) = *reinterpret_cast<const float4*>(&Ks[k*SPAD + tn*8 + 4]);
            mma8x8(acc, a8, b8);
        }
        __syncthreads();
    }

    #pragma unroll
    for (int i = 0; i < 8; i++) {
        #pragma unroll
        for (int j = 0; j < 4; j++) {
            Ssm[(tn*8 + 2*j    ) * TOK + tm*8 + i] = acc[i][j].x;
            Ssm[(tn*8 + 2*j + 1) * TOK + tm*8 + i] = acc[i][j].y;
        }
    }
    __syncthreads();

    if (tid < TOK) {
        const int i = tid;
        float mx = -1e30f;
        for (int j = 0; j < TOK; j++) mx = fmaxf(mx, Ssm[j*TOK + i]);
        float s = 0.f;
        for (int j = 0; j < TOK; j++) {
            float e = __expf((Ssm[j*TOK + i] - mx) * 0.125f);
            s += e;
            Ssm[j*TOK + i] = e;
        }
        float inv = 1.f / s;
        for (int j = 0; j < TOK; j++) Ssm[j*TOK + i] *= inv;
    }
    __syncthreads();

    float* Vs = sbuf;  // [128][VP]
    float* outbuf = (mode == 0) ? g_bufH : g_bufW;
    float* dbase0 = outbuf + ((size_t)b * INNER + head * DH) * HW;

    for (int d = 0; d < DH; d++) {
        #pragma unroll
        for (int it = 0; it < 16; it++) {
            int idx = tid + it * 256;
            int r  = idx >> 5;
            int c4 = (idx & 31) << 2;
            *reinterpret_cast<float4*>(&Vs[r*VP + c4]) =
                *reinterpret_cast<const float4*>(&vb[(size_t)d*HW + r*TOK + c4]);
        }
        __syncthreads();

        float2 oacc[8][4];
        #pragma unroll
        for (int i = 0; i < 8; i++)
            #pragma unroll
            for (int j = 0; j < 4; j++) oacc[i][j] = make_float2(0.f, 0.f);

        if (mode == 0) {
            #pragma unroll 4
            for (int k = 0; k < TOK; k++) {
                float a8[8], b8[8];
                *reinterpret_cast<float4*>(a8)     = *reinterpret_cast<const float4*>(&Ssm[k*TOK + tm*8]);
                *reinterpret_cast<float4*>(a8 + 4) = *reinterpret_cast<const float4*>(&Ssm[k*TOK + tm*8 + 4]);
                *reinterpret_cast<float4*>(b8)     = *reinterpret_cast<const float4*>(&Vs[k*VP + tn*8]);
                *reinterpret_cast<float4*>(b8 + 4) = *reinterpret_cast<const float4*>(&Vs[k*VP + tn*8 + 4]);
                mma8x8(oacc, a8, b8);
            }
            float* dstb = dbase0 + (size_t)d * HW;
            #pragma unroll
            for (int i = 0; i < 8; i++) {
                int tok = tm * 8 + i;
                float* dst = dstb + (size_t)tok * TOK + tn * 8;
                float4 v0 = make_float4(oacc[i][0].x, oacc[i][0].y, oacc[i][1].x, oacc[i][1].y);
                float4 v1 = make_float4(oacc[i][2].x, oacc[i][2].y, oacc[i][3].x, oacc[i][3].y);
                *reinterpret_cast<float4*>(dst)     = v0;
                *reinterpret_cast<float4*>(dst + 4) = v1;
            }
        } else {
            #pragma unroll 4
            for (int k = 0; k < TOK; k++) {
                float a8[8], b8[8];
                #pragma unroll
                for (int t = 0; t < 8; t++) a8[t] = Vs[(tm*8 + t)*VP + k];
                *reinterpret_cast<float4*>(b8)     = *reinterpret_cast<const float4*>(&Ssm[k*TOK + tn*8]);
                *reinterpret_cast<float4*>(b8 + 4) = *reinterpret_cast<const float4*>(&Ssm[k*TOK + tn*8 + 4]);
                mma8x8(oacc, a8, b8);
            }
            float* dstb = dbase0 + (size_t)d * HW;
            #pragma unroll
            for (int i = 0; i < 8; i++) {
                int hloc = tm * 8 + i;
                float* dst = dstb + (size_t)hloc * TOK + tn * 8;
                float4 v0 = make_float4(oacc[i][0].x, oacc[i][0].y, oacc[i][1].x, oacc[i][1].y);
                float4 v1 = make_float4(oacc[i][2].x, oacc[i][2].y, oacc[i][3].x, oacc[i][3].y);
                *reinterpret_cast<float4*>(dst)     = v0;
                *reinterpret_cast<float4*>(dst + 4) = v1;
            }
        }
        __syncthreads();
    }
}

// ============================================================
// K3: out = w_out @ (0.5*(bufH+bufW)) + b_out + x  via mma.sync
// CTA 128x128, K=512 in 8 slabs of 64. B built inline from bufH/bufW.
// ============================================================
#define K3AP 72    // A smem stride (bf16)
#define K3BP 136   // B smem stride (bf16), rows = k, cols = n

extern __shared__ __nv_bfloat16 k3_sm[];

__global__ void __launch_bounds__(256) out_mma_kernel(
    const float* __restrict__ x, const float* __restrict__ bout, float* __restrict__ out)
{
    __nv_bfloat16* As = k3_sm;                  // [2][128][K3AP]
    __nv_bfloat16* Bs = k3_sm + 2 * 128 * K3AP; // [2][64][K3BP]

    const int tid = threadIdx.x;
    const int lane = tid & 31, warp = tid >> 5;
    const int wm = warp >> 2, wn = warp & 3;
    const int n0 = blockIdx.x * 128;
    const int m0 = blockIdx.y * 128;
    const int b  = blockIdx.z;

    float acc[4][4][4];
    #pragma unroll
    for (int i = 0; i < 4; i++)
        #pragma unroll
        for (int j = 0; j < 4; j++)
            #pragma unroll
            for (int q = 0; q < 4; q++) acc[i][j][q] = 0.f;

    for (int s = 0; s < 8; s++) {
        const int k0 = s * 64;
        // A: wout rows m0..m0+127, cols k0..k0+63, both splits
        #pragma unroll
        for (int sp = 0; sp < 2; sp++) {
            const __nv_bfloat16* src = sp ? g_wo_lo : g_wo_hi;
            __nv_bfloat16* dst = As + sp * 128 * K3AP;
            #pragma unroll
            for (int it = 0; it < 4; it++) {
                int idx = tid + it * 256;
                int r = idx >> 3, c = (idx & 7) * 8;
                *reinterpret_cast<uint4*>(dst + r * K3AP + c) =
                    *reinterpret_cast<const uint4*>(src + (size_t)(m0 + r) * INNER + k0 + c);
            }
        }
        // B: average bufH/bufW, split, store [k][n]
        {
            __nv_bfloat16* Bh = Bs;
            __nv_bfloat16* Bl = Bs + 64 * K3BP;
            #pragma unroll
            for (int it = 0; it < 8; it++) {
                int idx = tid + it * 256;
                int r = idx >> 5, c = (idx & 31) * 4;
                size_t gi = ((size_t)b * INNER + k0 + r) * HW + n0 + c;
                float4 hv = *reinterpret_cast<const float4*>(g_bufH + gi);
                float4 wv = *reinterpret_cast<const float4*>(g_bufW + gi);
                float s0 = 0.5f * (hv.x + wv.x), s1 = 0.5f * (hv.y + wv.y);
                float s2 = 0.5f * (hv.z + wv.z), s3 = 0.5f * (hv.w + wv.w);
                __nv_bfloat16 h0 = __float2bfloat16(s0), h1 = __float2bfloat16(s1);
                __nv_bfloat16 h2 = __float2bfloat16(s2), h3 = __float2bfloat16(s3);
                __nv_bfloat16 l0 = __float2bfloat16(s0 - __bfloat162float(h0));
                __nv_bfloat16 l1 = __float2bfloat16(s1 - __bfloat162float(h1));
                __nv_bfloat16 l2 = __float2bfloat16(s2 - __bfloat162float(h2));
                __nv_bfloat16 l3 = __float2bfloat16(s3 - __bfloat162float(h3));
                *reinterpret_cast<__nv_bfloat162*>(Bh + r * K3BP + c)     = __nv_bfloat162(h0, h1);
                *reinterpret_cast<__nv_bfloat162*>(Bh + r * K3BP + c + 2) = __nv_bfloat162(h2, h3);
                *reinterpret_cast<__nv_bfloat162*>(Bl + r * K3BP + c)     = __nv_bfloat162(l0, l1);
                *reinterpret_cast<__nv_bfloat162*>(Bl + r * K3BP + c + 2) = __nv_bfloat162(l2, l3);
            }
        }
        __syncthreads();

        #pragma unroll
        for (int p = 0; p < 3; p++) {
            const __nv_bfloat16* Ab = As + (p == 2 ? 128 * K3AP : 0);
            const __nv_bfloat16* Bb = Bs + (p == 1 ? 64 * K3BP : 0);
            #pragma unroll
            for (int ks = 0; ks < 4; ks++) {
                const int kk = ks * 16;
                uint32_t af[4][4], bf2[4][2];
                #pragma unroll
                for (int mt = 0; mt < 4; mt++) {
                    uint32_t a = smem_u32(Ab + (wm * 64 + mt * 16 + (lane & 15)) * K3AP + kk + (lane >> 4) * 8);
                    ldsm4(a, af[mt][0], af[mt][1], af[mt][2], af[mt][3]);
                }
                #pragma unroll
                for (int np = 0; np < 2; np++) {
                    int krow = kk + (lane & 7) + ((lane >> 3) & 1) * 8;
                    int ncol = wn * 32 + np * 16 + ((lane >> 4) & 1) * 8;
                    uint32_t a = smem_u32(Bb + krow * K3BP + ncol);
                    ldsm4t(a, bf2[np*2][0], bf2[np*2][1], bf2[np*2+1][0], bf2[np*2+1][1]);
                }
                #pragma unroll
                for (int mt = 0; mt < 4; mt++)
                    #pragma unroll
                    for (int nt = 0; nt < 4; nt++)
                        mma16816(acc[mt][nt], af[mt], bf2[nt]);
            }
        }
        __syncthreads();
    }

    // epilogue: + bias + residual
    const int g = lane >> 2, tig = lane & 3;
    #pragma unroll
    for (int mt = 0; mt < 4; mt++) {
        int mbase = m0 + wm * 64 + mt * 16;
        #pragma unroll
        for (int half = 0; half < 2; half++) {
            int m = mbase + g + half * 8;
            float bias = bout[m];
            size_t rbase = ((size_t)b * CH + m) * HW + n0;
            #pragma unroll
            for (int nt = 0; nt < 4; nt++) {
                int col = wn * 32 + nt * 8 + tig * 2;
                float2 xv = *reinterpret_cast<const float2*>(x + rbase + col);
                *reinterpret_cast<float2*>(out + rbase + col) =
                    make_float2(acc[mt][nt][half*2]   + bias + xv.x,
                                acc[mt][nt][half*2+1] + bias + xv.y);
            }
        }
    }
}

// ============================================================
extern "C" void kernel_launch(void* const* d_in, const int* in_sizes, int n_in,
                              void* d_out, int out_size) {
    (void)in_sizes; (void)n_in; (void)out_size;
    const float* x    = (const float*)d_in[0];
    const float* wqkv = (const float*)d_in[1];
    const float* wout = (const float*)d_in[2];
    const float* bout = (const float*)d_in[3];
    float* out = (float*)d_out;

    const int attn_bytes = (TOK * TOK + TOK * VP) * 4;                 // 133120
    const int k1_bytes   = 4 * 128 * K1P * (int)sizeof(__nv_bfloat16); // 73728
    const int k3_bytes   = (2 * 128 * K3AP + 2 * 64 * K3BP) * (int)sizeof(__nv_bfloat16); // 71680
    cudaFuncSetAttribute(attn_kernel,    cudaFuncAttributeMaxDynamicSharedMemorySize, attn_bytes);
    cudaFuncSetAttribute(qkv_mma_kernel, cudaFuncAttributeMaxDynamicSharedMemorySize, k1_bytes);
    cudaFuncSetAttribute(out_mma_kernel, cudaFuncAttributeMaxDynamicSharedMemorySize, k3_bytes);

    convert_w_kernel<<<(NWQKV + NWOUT) / 256, 256>>>(wqkv, wout);
    transpose_x_kernel<<<dim3(HW / 32, CH / 32, BATCH), 256>>>(x);
    qkv_mma_kernel<<<dim3(HW / 128, 1536 / 128, BATCH), 256, k1_bytes>>>();
    attn_kernel<<<dim3(BATCH * HEADS, 2), 256, attn_bytes>>>();
    out_mma_kernel<<<dim3(HW / 128, CH / 128, BATCH), 256, k3_bytes>>>(x, bout, out);
}

// round 6
// speedup vs baseline: 1.7844x; 1.3009x over previous
#include <cuda_runtime.h>
#include <cuda_bf16.h>
#include <cstdint>

#define BATCH 8
#define CH    256
#define HW    16384   // 128*128
#define TOK   128
#define HEADS 8
#define DH    64
#define INNER 512

// ---- scratch (device globals; no runtime allocation) ----
__device__ float g_bufH[(size_t)BATCH*INNER*HW];   // row-attn output  [b][o][hw]
__device__ float g_bufW[(size_t)BATCH*INNER*HW];   // col-attn output  [b][o][hw]
// bf16 split operands
__device__ __nv_bfloat16 g_w_hi[(size_t)3*INNER*CH];
__device__ __nv_bfloat16 g_w_lo[(size_t)3*INNER*CH];
__device__ __nv_bfloat16 g_wo_hi[(size_t)CH*INNER];
__device__ __nv_bfloat16 g_wo_lo[(size_t)CH*INNER];
__device__ __nv_bfloat16 g_xt_hi[(size_t)BATCH*HW*CH];  // [b][hw][c]
__device__ __nv_bfloat16 g_xt_lo[(size_t)BATCH*HW*CH];
// q/k/v bf16 hi/lo: [b][o=head*64+d][hw]
__device__ __nv_bfloat16 g_q_hi[(size_t)BATCH*INNER*HW];
__device__ __nv_bfloat16 g_q_lo[(size_t)BATCH*INNER*HW];
__device__ __nv_bfloat16 g_k_hi[(size_t)BATCH*INNER*HW];
__device__ __nv_bfloat16 g_k_lo[(size_t)BATCH*INNER*HW];
__device__ __nv_bfloat16 g_v_hi[(size_t)BATCH*INNER*HW];
__device__ __nv_bfloat16 g_v_lo[(size_t)BATCH*INNER*HW];

// ============================================================
// helpers
// ============================================================
__device__ __forceinline__ uint32_t smem_u32(const void* p) {
    uint32_t a;
    asm("{ .reg .u64 t; cvta.to.shared.u64 t, %1; cvt.u32.u64 %0, t; }" : "=r"(a) : "l"(p));
    return a;
}
__device__ __forceinline__ void ldsm4(uint32_t a, uint32_t& r0, uint32_t& r1, uint32_t& r2, uint32_t& r3) {
    asm volatile("ldmatrix.sync.aligned.m8n8.x4.shared.b16 {%0,%1,%2,%3}, [%4];"
                 : "=r"(r0),"=r"(r1),"=r"(r2),"=r"(r3) : "r"(a));
}
__device__ __forceinline__ void ldsm4t(uint32_t a, uint32_t& r0, uint32_t& r1, uint32_t& r2, uint32_t& r3) {
    asm volatile("ldmatrix.sync.aligned.m8n8.x4.trans.shared.b16 {%0,%1,%2,%3}, [%4];"
                 : "=r"(r0),"=r"(r1),"=r"(r2),"=r"(r3) : "r"(a));
}
__device__ __forceinline__ void mma16816(float* d, const uint32_t* a, const uint32_t* b) {
    asm volatile("mma.sync.aligned.m16n8k16.row.col.f32.bf16.bf16.f32 "
                 "{%0,%1,%2,%3}, {%4,%5,%6,%7}, {%8,%9}, {%0,%1,%2,%3};"
                 : "+f"(d[0]),"+f"(d[1]),"+f"(d[2]),"+f"(d[3])
                 : "r"(a[0]),"r"(a[1]),"r"(a[2]),"r"(a[3]), "r"(b[0]),"r"(b[1]));
}
__device__ __forceinline__ void bf16_split(float v, __nv_bfloat16& h, __nv_bfloat16& l) {
    h = __float2bfloat16(v);
    l = __float2bfloat16(v - __bfloat162float(h));
}

// ============================================================
// K0a: split w_qkv and w_out into bf16 hi/lo
// ============================================================
#define NWQKV (3*INNER*CH)   // 393216
#define NWOUT (CH*INNER)     // 131072
__global__ void __launch_bounds__(256) convert_w_kernel(
    const float* __restrict__ wqkv, const float* __restrict__ wout)
{
    int i = blockIdx.x * 256 + threadIdx.x;
    if (i < NWQKV) {
        __nv_bfloat16 h, l;
        bf16_split(wqkv[i], h, l);
        g_w_hi[i] = h; g_w_lo[i] = l;
    } else {
        int j = i - NWQKV;
        __nv_bfloat16 h, l;
        bf16_split(wout[j], h, l);
        g_wo_hi[j] = h; g_wo_lo[j] = l;
    }
}

// ============================================================
// K0b: transpose x [b][c][hw] -> xt [b][hw][c], split bf16 hi/lo
// ============================================================
__global__ void __launch_bounds__(256) transpose_x_kernel(const float* __restrict__ x) {
    __shared__ float ts[32][33];
    const int b = blockIdx.z, c0 = blockIdx.y * 32, hw0 = blockIdx.x * 32;
    const int tx = threadIdx.x & 31, ty = threadIdx.x >> 5;
    const float* xb = x + ((size_t)b * CH + c0) * HW + hw0;
    #pragma unroll
    for (int i = 0; i < 4; i++) {
        int c = ty + i * 8;
        ts[c][tx] = xb[(size_t)c * HW + tx];
    }
    __syncthreads();
    size_t ob = ((size_t)b * HW + hw0) * CH + c0;
    #pragma unroll
    for (int i = 0; i < 4; i++) {
        int r = ty + i * 8;
        __nv_bfloat16 h, l;
        bf16_split(ts[tx][r], h, l);
        g_xt_hi[ob + (size_t)r * CH + tx] = h;
        g_xt_lo[ob + (size_t)r * CH + tx] = l;
    }
}

// ============================================================
// K1: qkv = w_qkv @ x via mma.sync bf16 3-pass split
// epilogue writes bf16 hi/lo q/k/v.
// ============================================================
#define K1P 72

extern __shared__ __nv_bfloat16 k1_sm[];

__global__ void __launch_bounds__(256) qkv_mma_kernel() {
    __nv_bfloat16* As = k1_sm;
    __nv_bfloat16* Bs = k1_sm + 2 * 128 * K1P;

    const int tid = threadIdx.x;
    const int lane = tid & 31, warp = tid >> 5;
    const int wm = warp >> 2, wn = warp & 3;
    const int n0 = blockIdx.x * 128;
    const int m0 = blockIdx.y * 128;
    const int b  = blockIdx.z;

    float acc[4][4][4];
    #pragma unroll
    for (int i = 0; i < 4; i++)
        #pragma unroll
        for (int j = 0; j < 4; j++)
            #pragma unroll
            for (int q = 0; q < 4; q++) acc[i][j][q] = 0.f;

    for (int s = 0; s < 4; s++) {
        const int k0 = s * 64;
        #pragma unroll
        for (int sp = 0; sp < 2; sp++) {
            const __nv_bfloat16* src = sp ? g_w_lo : g_w_hi;
            __nv_bfloat16* dst = As + sp * 128 * K1P;
            #pragma unroll
            for (int it = 0; it < 4; it++) {
                int idx = tid + it * 256;
                int r = idx >> 3, c = (idx & 7) * 8;
                *reinterpret_cast<uint4*>(dst + r * K1P + c) =
                    *reinterpret_cast<const uint4*>(src + (size_t)(m0 + r) * CH + k0 + c);
            }
        }
        #pragma unroll
        for (int sp = 0; sp < 2; sp++) {
            const __nv_bfloat16* src = sp ? g_xt_lo : g_xt_hi;
            __nv_bfloat16* dst = Bs + sp * 128 * K1P;
            #pragma unroll
            for (int it = 0; it < 4; it++) {
                int idx = tid + it * 256;
                int r = idx >> 3, c = (idx & 7) * 8;
                *reinterpret_cast<uint4*>(dst + r * K1P + c) =
                    *reinterpret_cast<const uint4*>(src + ((size_t)b * HW + n0 + r) * CH + k0 + c);
            }
        }
        __syncthreads();

        #pragma unroll
        for (int p = 0; p < 3; p++) {
            const __nv_bfloat16* Ab = As + (p == 2 ? 128 * K1P : 0);
            const __nv_bfloat16* Bb = Bs + (p == 1 ? 128 * K1P : 0);
            #pragma unroll
            for (int ks = 0; ks < 4; ks++) {
                const int kk = ks * 16;
                uint32_t af[4][4], bf2[4][2];
                #pragma unroll
                for (int mt = 0; mt < 4; mt++) {
                    uint32_t a = smem_u32(Ab + (wm * 64 + mt * 16 + (lane & 15)) * K1P + kk + (lane >> 4) * 8);
                    ldsm4(a, af[mt][0], af[mt][1], af[mt][2], af[mt][3]);
                }
                #pragma unroll
                for (int np = 0; np < 2; np++) {
                    int nrow = wn * 32 + np * 16 + (lane & 7) + ((lane >> 4) & 1) * 8;
                    int kcol = kk + ((lane >> 3) & 1) * 8;
                    uint32_t a = smem_u32(Bb + nrow * K1P + kcol);
                    ldsm4(a, bf2[np*2][0], bf2[np*2][1], bf2[np*2+1][0], bf2[np*2+1][1]);
                }
                #pragma unroll
                for (int mt = 0; mt < 4; mt++)
                    #pragma unroll
                    for (int nt = 0; nt < 4; nt++)
                        mma16816(acc[mt][nt], af[mt], bf2[nt]);
            }
        }
        __syncthreads();
    }

    // epilogue -> q/k/v bf16 hi/lo
    const int g = lane >> 2, tig = lane & 3;
    #pragma unroll
    for (int mt = 0; mt < 4; mt++) {
        int mbase = m0 + wm * 64 + mt * 16;
        #pragma unroll
        for (int half = 0; half < 2; half++) {
            int m = mbase + g + half * 8;
            int kind = m >> 9, oo = m & 511;
            __nv_bfloat16 *dh, *dl;
            if (kind == 0)      { dh = g_q_hi; dl = g_q_lo; }
            else if (kind == 1) { dh = g_k_hi; dl = g_k_lo; }
            else                { dh = g_v_hi; dl = g_v_lo; }
            size_t rbase = ((size_t)b * INNER + oo) * HW + n0;
            #pragma unroll
            for (int nt = 0; nt < 4; nt++) {
                int col = wn * 32 + nt * 8 + tig * 2;
                __nv_bfloat16 h0, l0, h1, l1;
                bf16_split(acc[mt][nt][half*2],   h0, l0);
                bf16_split(acc[mt][nt][half*2+1], h1, l1);
                *reinterpret_cast<__nv_bfloat162*>(dh + rbase + col) = __nv_bfloat162(h0, h1);
                *reinterpret_cast<__nv_bfloat162*>(dl + rbase + col) = __nv_bfloat162(l0, l1);
            }
        }
    }
}

// ============================================================
// K2: axial attention via mma.sync bf16 3-pass split
// grid (64 = b*head, 2 = mode). 256 threads, warp grid 2m x 4n.
// ============================================================
#define PS 136   // bf16 row stride for P/V/mode-1 tiles
#define QP 72    // bf16 row stride for mode-0 QK tiles

// smem byte offsets
#define AT_S   0                       // Ssm fp32 [128][128] = 65536
#define AT_PH  65536                   // Ps hi [128][PS] = 34816
#define AT_PL  100352                  // Ps lo
#define AT_T   135168                  // tiles / V region (73728 max)
#define AT_SMEM 208896

extern __shared__ char at_sm[];

__global__ void __launch_bounds__(256) attn_mma_kernel()
{
    float* Ssm = reinterpret_cast<float*>(at_sm + AT_S);
    __nv_bfloat16* Ph = reinterpret_cast<__nv_bfloat16*>(at_sm + AT_PH);
    __nv_bfloat16* Pl = reinterpret_cast<__nv_bfloat16*>(at_sm + AT_PL);

    const int tid = threadIdx.x;
    const int lane = tid & 31, warp = tid >> 5;
    const int wm = warp >> 2, wn = warp & 3;
    const int g = lane >> 2, tig = lane & 3;
    const int bh = blockIdx.x, mode = blockIdx.y;
    const int b = bh >> 3, head = bh & 7;

    const size_t pbase = ((size_t)b * INNER + head * DH) * HW;
    const __nv_bfloat16* __restrict__ qh = g_q_hi + pbase;
    const __nv_bfloat16* __restrict__ ql = g_q_lo + pbase;
    const __nv_bfloat16* __restrict__ kh = g_k_hi + pbase;
    const __nv_bfloat16* __restrict__ kl = g_k_lo + pbase;
    const __nv_bfloat16* __restrict__ vh = g_v_hi + pbase;
    const __nv_bfloat16* __restrict__ vl = g_v_lo + pbase;

    // ================= phase 1: S = Q K^T =================
    {
        float acc[4][4][4];
        #pragma unroll
        for (int i = 0; i < 4; i++)
            #pragma unroll
            for (int j = 0; j < 4; j++)
                #pragma unroll
                for (int q = 0; q < 4; q++) acc[i][j][q] = 0.f;

        const __nv_bfloat16* srcs[4] = { qh, ql, kh, kl };

        for (int s = 0; s < 128; s++) {
            const int d = s >> 1, off = (s & 1) * 64;

            if (mode == 0) {
                // tiles [token 128][k 64] stride QP; 4 regions of 18432 B
                #pragma unroll
                for (int t = 0; t < 4; t++) {
                    __nv_bfloat16* dst = reinterpret_cast<__nv_bfloat16*>(at_sm + AT_T + t * 18432);
                    const __nv_bfloat16* src = srcs[t] + (size_t)d * HW + off;
                    #pragma unroll
                    for (int it = 0; it < 4; it++) {
                        int idx = tid + it * 256;
                        int r = idx >> 3, c = (idx & 7) * 8;
                        *reinterpret_cast<uint4*>(dst + r * QP + c) =
                            *reinterpret_cast<const uint4*>(src + r * TOK + c);
                    }
                }
            } else {
                // tiles [k=h 64][token 128] stride PS; 4 regions of 17408 B
                #pragma unroll
                for (int t = 0; t < 4; t++) {
                    __nv_bfloat16* dst = reinterpret_cast<__nv_bfloat16*>(at_sm + AT_T + t * 17408);
                    const __nv_bfloat16* src = srcs[t] + (size_t)d * HW + (size_t)off * TOK;
                    #pragma unroll
                    for (int it = 0; it < 4; it++) {
                        int idx = tid + it * 256;
                        int r = idx >> 4, c = (idx & 15) * 8;
                        *reinterpret_cast<uint4*>(dst + r * PS + c) =
                            *reinterpret_cast<const uint4*>(src + r * TOK + c);
                    }
                }
            }
            __syncthreads();

            #pragma unroll
            for (int p = 0; p < 3; p++) {
                const int ai = (p == 2) ? 1 : 0;       // Q lo on pass 2
                const int bi = (p == 1) ? 3 : 2;       // K lo on pass 1
                if (mode == 0) {
                    const __nv_bfloat16* Ab = reinterpret_cast<__nv_bfloat16*>(at_sm + AT_T + ai * 18432);
                    const __nv_bfloat16* Bb = reinterpret_cast<__nv_bfloat16*>(at_sm + AT_T + bi * 18432);
                    #pragma unroll
                    for (int ks = 0; ks < 4; ks++) {
                        const int kk = ks * 16;
                        uint32_t af[4][4], bf2[4][2];
                        #pragma unroll
                        for (int mt = 0; mt < 4; mt++) {
                            uint32_t a = smem_u32(Ab + (wm*64 + mt*16 + (lane & 15)) * QP + kk + (lane >> 4) * 8);
                            ldsm4(a, af[mt][0], af[mt][1], af[mt][2], af[mt][3]);
                        }
                        #pragma unroll
                        for (int np = 0; np < 2; np++) {
                            int nrow = wn*32 + np*16 + (lane & 7) + ((lane >> 4) & 1) * 8;
                            int kcol = kk + ((lane >> 3) & 1) * 8;
                            uint32_t a = smem_u32(Bb + nrow * QP + kcol);
                            ldsm4(a, bf2[np*2][0], bf2[np*2][1], bf2[np*2+1][0], bf2[np*2+1][1]);
                        }
                        #pragma unroll
                        for (int mt = 0; mt < 4; mt++)
                            #pragma unroll
                            for (int nt = 0; nt < 4; nt++)
                                mma16816(acc[mt][nt], af[mt], bf2[nt]);
                    }
                } else {
                    const __nv_bfloat16* Ab = reinterpret_cast<__nv_bfloat16*>(at_sm + AT_T + ai * 17408);
                    const __nv_bfloat16* Bb = reinterpret_cast<__nv_bfloat16*>(at_sm + AT_T + bi * 17408);
                    #pragma unroll
                    for (int ks = 0; ks < 4; ks++) {
                        const int kk = ks * 16;
                        uint32_t af[4][4], bf2[4][2];
                        #pragma unroll
                        for (int mt = 0; mt < 4; mt++) {   // trans-A from [k][m]
                            uint32_t a = smem_u32(Ab + (kk + (lane & 7) + ((lane >> 4) & 1) * 8) * PS
                                                     + wm*64 + mt*16 + ((lane >> 3) & 1) * 8);
                            ldsm4t(a, af[mt][0], af[mt][1], af[mt][2], af[mt][3]);
                        }
                        #pragma unroll
                        for (int np = 0; np < 2; np++) {   // trans-B from [k][n]
                            int krow = kk + (lane & 7) + ((lane >> 3) & 1) * 8;
                            int ncol = wn*32 + np*16 + ((lane >> 4) & 1) * 8;
                            uint32_t a = smem_u32(Bb + krow * PS + ncol);
                            ldsm4t(a, bf2[np*2][0], bf2[np*2][1], bf2[np*2+1][0], bf2[np*2+1][1]);
                        }
                        #pragma unroll
                        for (int mt = 0; mt < 4; mt++)
                            #pragma unroll
                            for (int nt = 0; nt < 4; nt++)
                                mma16816(acc[mt][nt], af[mt], bf2[nt]);
                    }
                }
            }
            __syncthreads();
        }

        // store logits S[j][i]
        #pragma unroll
        for (int mt = 0; mt < 4; mt++) {
            int i0 = wm*64 + mt*16 + g;
            #pragma unroll
            for (int nt = 0; nt < 4; nt++) {
                int j0 = wn*32 + nt*8 + tig*2;
                Ssm[j0 * TOK + i0]           = acc[mt][nt][0];
                Ssm[(j0+1) * TOK + i0]       = acc[mt][nt][1];
                Ssm[j0 * TOK + i0 + 8]       = acc[mt][nt][2];
                Ssm[(j0+1) * TOK + i0 + 8]   = acc[mt][nt][3];
            }
        }
    }
    __syncthreads();

    // ================= softmax over j, write P hi/lo =================
    if (tid < TOK) {
        const int i = tid;
        float mx = -1e30f;
        for (int j = 0; j < TOK; j++) mx = fmaxf(mx, Ssm[j * TOK + i]);
        float s = 0.f;
        for (int j = 0; j < TOK; j++) {
            float e = __expf((Ssm[j * TOK + i] - mx) * 0.125f);
            s += e;
            Ssm[j * TOK + i] = e;
        }
        float inv = 1.f / s;
        for (int j = 0; j < TOK; j++) {
            float pv = Ssm[j * TOK + i] * inv;
            __nv_bfloat16 h, l;
            bf16_split(pv, h, l);
            Ph[j * PS + i] = h;
            Pl[j * PS + i] = l;
        }
    }
    __syncthreads();

    // ================= phase 2: O = P V =================
    __nv_bfloat16* Vh = reinterpret_cast<__nv_bfloat16*>(at_sm + AT_T);
    __nv_bfloat16* Vl = Vh + 128 * PS;
    float* outp = ((mode == 0) ? g_bufH : g_bufW) + pbase;

    for (int d = 0; d < DH; d++) {
        #pragma unroll
        for (int sp = 0; sp < 2; sp++) {
            const __nv_bfloat16* src = (sp ? vl : vh) + (size_t)d * HW;
            __nv_bfloat16* dst = sp ? Vl : Vh;
            #pragma unroll
            for (int it = 0; it < 8; it++) {
                int idx = tid + it * 256;
                int r = idx >> 4, c = (idx & 15) * 8;
                *reinterpret_cast<uint4*>(dst + r * PS + c) =
                    *reinterpret_cast<const uint4*>(src + r * TOK + c);
            }
        }
        __syncthreads();

        float oacc[4][4][4];
        #pragma unroll
        for (int i = 0; i < 4; i++)
            #pragma unroll
            for (int j = 0; j < 4; j++)
                #pragma unroll
                for (int q = 0; q < 4; q++) oacc[i][j][q] = 0.f;

        #pragma unroll
        for (int p = 0; p < 3; p++) {
            if (mode == 0) {
                // A = P[i][j] from Ps[j][i] (trans-A); B = V[j][w] from Vs[j][w] (trans-B)
                const __nv_bfloat16* Ab = (p == 2) ? Pl : Ph;
                const __nv_bfloat16* Bb = (p == 1) ? Vl : Vh;
                #pragma unroll
                for (int ks = 0; ks < 8; ks++) {
                    const int kk = ks * 16;
                    uint32_t af[4][4], bf2[4][2];
                    #pragma unroll
                    for (int mt = 0; mt < 4; mt++) {
                        uint32_t a = smem_u32(Ab + (kk + (lane & 7) + ((lane >> 4) & 1) * 8) * PS
                                                 + wm*64 + mt*16 + ((lane >> 3) & 1) * 8);
                        ldsm4t(a, af[mt][0], af[mt][1], af[mt][2], af[mt][3]);
                    }
                    #pragma unroll
                    for (int np = 0; np < 2; np++) {
                        int krow = kk + (lane & 7) + ((lane >> 3) & 1) * 8;
                        int ncol = wn*32 + np*16 + ((lane >> 4) & 1) * 8;
                        uint32_t a = smem_u32(Bb + krow * PS + ncol);
                        ldsm4t(a, bf2[np*2][0], bf2[np*2][1], bf2[np*2+1][0], bf2[np*2+1][1]);
                    }
                    #pragma unroll
                    for (int mt = 0; mt < 4; mt++)
                        #pragma unroll
                        for (int nt = 0; nt < 4; nt++)
                            mma16816(oacc[mt][nt], af[mt], bf2[nt]);
                }
            } else {
                // A = V[h][j] from Vs rows (plain); B = P[j][w] from Ps[j][i] (trans-B)
                const __nv_bfloat16* Ab = (p == 2) ? Vl : Vh;
                const __nv_bfloat16* Bb = (p == 1) ? Pl : Ph;
                #pragma unroll
                for (int ks = 0; ks < 8; ks++) {
                    const int kk = ks * 16;
                    uint32_t af[4][4], bf2[4][2];
                    #pragma unroll
                    for (int mt = 0; mt < 4; mt++) {
                        uint32_t a = smem_u32(Ab + (wm*64 + mt*16 + (lane & 15)) * PS + kk + (lane >> 4) * 8);
                        ldsm4(a, af[mt][0], af[mt][1], af[mt][2], af[mt][3]);
                    }
                    #pragma unroll
                    for (int np = 0; np < 2; np++) {
                        int krow = kk + (lane & 7) + ((lane >> 3) & 1) * 8;
                        int ncol = wn*32 + np*16 + ((lane >> 4) & 1) * 8;
                        uint32_t a = smem_u32(Bb + krow * PS + ncol);
                        ldsm4t(a, bf2[np*2][0], bf2[np*2][1], bf2[np*2+1][0], bf2[np*2+1][1]);
                    }
                    #pragma unroll
                    for (int mt = 0; mt < 4; mt++)
                        #pragma unroll
                        for (int nt = 0; nt < 4; nt++)
                            mma16816(oacc[mt][nt], af[mt], bf2[nt]);
                }
            }
        }

        // epilogue: out_plane[m][n] -> outp[d][m][n] (coalesced, both modes)
        float* dstb = outp + (size_t)d * HW;
        #pragma unroll
        for (int mt = 0; mt < 4; mt++) {
            #pragma unroll
            for (int half = 0; half < 2; half++) {
                int m = wm*64 + mt*16 + g + half*8;
                float* rowp = dstb + (size_t)m * TOK;
                #pragma unroll
                for (int nt = 0; nt < 4; nt++) {
                    int col = wn*32 + nt*8 + tig*2;
                    *reinterpret_cast<float2*>(rowp + col) =
                        make_float2(oacc[mt][nt][half*2], oacc[mt][nt][half*2+1]);
                }
            }
        }
        __syncthreads();
    }
}

// ============================================================
// K3: out = w_out @ (0.5*(bufH+bufW)) + b_out + x  via mma.sync
// ============================================================
#define K3AP 72
#define K3BP 136

extern __shared__ __nv_bfloat16 k3_sm[];

__global__ void __launch_bounds__(256) out_mma_kernel(
    const float* __restrict__ x, const float* __restrict__ bout, float* __restrict__ out)
{
    __nv_bfloat16* As = k3_sm;
    __nv_bfloat16* Bs = k3_sm + 2 * 128 * K3AP;

    const int tid = threadIdx.x;
    const int lane = tid & 31, warp = tid >> 5;
    const int wm = warp >> 2, wn = warp & 3;
    const int n0 = blockIdx.x * 128;
    const int m0 = blockIdx.y * 128;
    const int b  = blockIdx.z;

    float acc[4][4][4];
    #pragma unroll
    for (int i = 0; i < 4; i++)
        #pragma unroll
        for (int j = 0; j < 4; j++)
            #pragma unroll
            for (int q = 0; q < 4; q++) acc[i][j][q] = 0.f;

    for (int s = 0; s < 8; s++) {
        const int k0 = s * 64;
        #pragma unroll
        for (int sp = 0; sp < 2; sp++) {
            const __nv_bfloat16* src = sp ? g_wo_lo : g_wo_hi;
            __nv_bfloat16* dst = As + sp * 128 * K3AP;
            #pragma unroll
            for (int it = 0; it < 4; it++) {
                int idx = tid + it * 256;
                int r = idx >> 3, c = (idx & 7) * 8;
                *reinterpret_cast<uint4*>(dst + r * K3AP + c) =
                    *reinterpret_cast<const uint4*>(src + (size_t)(m0 + r) * INNER + k0 + c);
            }
        }
        {
            __nv_bfloat16* Bh = Bs;
            __nv_bfloat16* Bl = Bs + 64 * K3BP;
            #pragma unroll
            for (int it = 0; it < 8; it++) {
                int idx = tid + it * 256;
                int r = idx >> 5, c = (idx & 31) * 4;
                size_t gi = ((size_t)b * INNER + k0 + r) * HW + n0 + c;
                float4 hv = *reinterpret_cast<const float4*>(g_bufH + gi);
                float4 wv = *reinterpret_cast<const float4*>(g_bufW + gi);
                float s0 = 0.5f * (hv.x + wv.x), s1 = 0.5f * (hv.y + wv.y);
                float s2 = 0.5f * (hv.z + wv.z), s3 = 0.5f * (hv.w + wv.w);
                __nv_bfloat16 h0, l0, h1, l1, h2, l2, h3, l3;
                bf16_split(s0, h0, l0); bf16_split(s1, h1, l1);
                bf16_split(s2, h2, l2); bf16_split(s3, h3, l3);
                *reinterpret_cast<__nv_bfloat162*>(Bh + r * K3BP + c)     = __nv_bfloat162(h0, h1);
                *reinterpret_cast<__nv_bfloat162*>(Bh + r * K3BP + c + 2) = __nv_bfloat162(h2, h3);
                *reinterpret_cast<__nv_bfloat162*>(Bl + r * K3BP + c)     = __nv_bfloat162(l0, l1);
                *reinterpret_cast<__nv_bfloat162*>(Bl + r * K3BP + c + 2) = __nv_bfloat162(l2, l3);
            }
        }
        __syncthreads();

        #pragma unroll
        for (int p = 0; p < 3; p++) {
            const __nv_bfloat16* Ab = As + (p == 2 ? 128 * K3AP : 0);
            const __nv_bfloat16* Bb = Bs + (p == 1 ? 64 * K3BP : 0);
            #pragma unroll
            for (int ks = 0; ks < 4; ks++) {
                const int kk = ks * 16;
                uint32_t af[4][4], bf2[4][2];
                #pragma unroll
                for (int mt = 0; mt < 4; mt++) {
                    uint32_t a = smem_u32(Ab + (wm * 64 + mt * 16 + (lane & 15)) * K3AP + kk + (lane >> 4) * 8);
                    ldsm4(a, af[mt][0], af[mt][1], af[mt][2], af[mt][3]);
                }
                #pragma unroll
                for (int np = 0; np < 2; np++) {
                    int krow = kk + (lane & 7) + ((lane >> 3) & 1) * 8;
                    int ncol = wn * 32 + np * 16 + ((lane >> 4) & 1) * 8;
                    uint32_t a = smem_u32(Bb + krow * K3BP + ncol);
                    ldsm4t(a, bf2[np*2][0], bf2[np*2][1], bf2[np*2+1][0], bf2[np*2+1][1]);
                }
                #pragma unroll
                for (int mt = 0; mt < 4; mt++)
                    #pragma unroll
                    for (int nt = 0; nt < 4; nt++)
                        mma16816(acc[mt][nt], af[mt], bf2[nt]);
            }
        }
        __syncthreads();
    }

    const int g = lane >> 2, tig = lane & 3;
    #pragma unroll
    for (int mt = 0; mt < 4; mt++) {
        int mbase = m0 + wm * 64 + mt * 16;
        #pragma unroll
        for (int half = 0; half < 2; half++) {
            int m = mbase + g + half * 8;
            float bias = bout[m];
            size_t rbase = ((size_t)b * CH + m) * HW + n0;
            #pragma unroll
            for (int nt = 0; nt < 4; nt++) {
                int col = wn * 32 + nt * 8 + tig * 2;
                float2 xv = *reinterpret_cast<const float2*>(x + rbase + col);
                *reinterpret_cast<float2*>(out + rbase + col) =
                    make_float2(acc[mt][nt][half*2]   + bias + xv.x,
                                acc[mt][nt][half*2+1] + bias + xv.y);
            }
        }
    }
}

// ============================================================
extern "C" void kernel_launch(void* const* d_in, const int* in_sizes, int n_in,
                              void* d_out, int out_size) {
    (void)in_sizes; (void)n_in; (void)out_size;
    const float* x    = (const float*)d_in[0];
    const float* wqkv = (const float*)d_in[1];
    const float* wout = (const float*)d_in[2];
    const float* bout = (const float*)d_in[3];
    float* out = (float*)d_out;

    const int k1_bytes = 4 * 128 * K1P * (int)sizeof(__nv_bfloat16);                       // 73728
    const int k3_bytes = (2 * 128 * K3AP + 2 * 64 * K3BP) * (int)sizeof(__nv_bfloat16);    // 71680
    cudaFuncSetAttribute(qkv_mma_kernel,  cudaFuncAttributeMaxDynamicSharedMemorySize, k1_bytes);
    cudaFuncSetAttribute(attn_mma_kernel, cudaFuncAttributeMaxDynamicSharedMemorySize, AT_SMEM);
    cudaFuncSetAttribute(out_mma_kernel,  cudaFuncAttributeMaxDynamicSharedMemorySize, k3_bytes);

    convert_w_kernel<<<(NWQKV + NWOUT) / 256, 256>>>(wqkv, wout);
    transpose_x_kernel<<<dim3(HW / 32, CH / 32, BATCH), 256>>>(x);
    qkv_mma_kernel<<<dim3(HW / 128, 1536 / 128, BATCH), 256, k1_bytes>>>();
    attn_mma_kernel<<<dim3(BATCH * HEADS, 2), 256, AT_SMEM>>>();
    out_mma_kernel<<<dim3(HW / 128, CH / 128, BATCH), 256, k3_bytes>>>(x, bout, out);
}

// round 7
// speedup vs baseline: 1.8296x; 1.0253x over previous
#include <cuda_runtime.h>
#include <cuda_bf16.h>
#include <cstdint>

#define BATCH 8
#define CH    256
#define HW    16384   // 128*128
#define TOK   128
#define HEADS 8
#define DH    64
#define INNER 512

// ---- scratch (device globals; no runtime allocation) ----
__device__ float g_bufH[(size_t)BATCH*INNER*HW];   // row-attn output  [b][o][hw]
__device__ float g_bufW[(size_t)BATCH*INNER*HW];   // col-attn output  [b][o][hw]
// bf16 split operands
__device__ __nv_bfloat16 g_w_hi[(size_t)3*INNER*CH];
__device__ __nv_bfloat16 g_w_lo[(size_t)3*INNER*CH];
__device__ __nv_bfloat16 g_wo_hi[(size_t)CH*INNER];
__device__ __nv_bfloat16 g_wo_lo[(size_t)CH*INNER];
__device__ __nv_bfloat16 g_xt_hi[(size_t)BATCH*HW*CH];  // [b][hw][c]
__device__ __nv_bfloat16 g_xt_lo[(size_t)BATCH*HW*CH];
// q/k/v bf16 hi/lo: [b][o=head*64+d][hw]
__device__ __nv_bfloat16 g_q_hi[(size_t)BATCH*INNER*HW];
__device__ __nv_bfloat16 g_q_lo[(size_t)BATCH*INNER*HW];
__device__ __nv_bfloat16 g_k_hi[(size_t)BATCH*INNER*HW];
__device__ __nv_bfloat16 g_k_lo[(size_t)BATCH*INNER*HW];
__device__ __nv_bfloat16 g_v_hi[(size_t)BATCH*INNER*HW];
__device__ __nv_bfloat16 g_v_lo[(size_t)BATCH*INNER*HW];

// ============================================================
// helpers
// ============================================================
__device__ __forceinline__ uint32_t smem_u32(const void* p) {
    uint32_t a;
    asm("{ .reg .u64 t; cvta.to.shared.u64 t, %1; cvt.u32.u64 %0, t; }" : "=r"(a) : "l"(p));
    return a;
}
__device__ __forceinline__ void ldsm4(uint32_t a, uint32_t& r0, uint32_t& r1, uint32_t& r2, uint32_t& r3) {
    asm volatile("ldmatrix.sync.aligned.m8n8.x4.shared.b16 {%0,%1,%2,%3}, [%4];"
                 : "=r"(r0),"=r"(r1),"=r"(r2),"=r"(r3) : "r"(a));
}
__device__ __forceinline__ void ldsm4t(uint32_t a, uint32_t& r0, uint32_t& r1, uint32_t& r2, uint32_t& r3) {
    asm volatile("ldmatrix.sync.aligned.m8n8.x4.trans.shared.b16 {%0,%1,%2,%3}, [%4];"
                 : "=r"(r0),"=r"(r1),"=r"(r2),"=r"(r3) : "r"(a));
}
__device__ __forceinline__ void mma16816(float* d, const uint32_t* a, const uint32_t* b) {
    asm volatile("mma.sync.aligned.m16n8k16.row.col.f32.bf16.bf16.f32 "
                 "{%0,%1,%2,%3}, {%4,%5,%6,%7}, {%8,%9}, {%0,%1,%2,%3};"
                 : "+f"(d[0]),"+f"(d[1]),"+f"(d[2]),"+f"(d[3])
                 : "r"(a[0]),"r"(a[1]),"r"(a[2]),"r"(a[3]), "r"(b[0]),"r"(b[1]));
}
__device__ __forceinline__ void bf16_split(float v, __nv_bfloat16& h, __nv_bfloat16& l) {
    h = __float2bfloat16(v);
    l = __float2bfloat16(v - __bfloat162float(h));
}
__device__ __forceinline__ void cp16(uint32_t dst, const void* src) {
    asm volatile("cp.async.cg.shared.global [%0], [%1], 16;" :: "r"(dst), "l"(src));
}
__device__ __forceinline__ void cp_commit() { asm volatile("cp.async.commit_group;" ::: "memory"); }
template<int N> __device__ __forceinline__ void cp_wait() {
    asm volatile("cp.async.wait_group %0;" :: "n"(N) : "memory");
}

// ============================================================
// K0a: split w_qkv and w_out into bf16 hi/lo
// ============================================================
#define NWQKV (3*INNER*CH)   // 393216
#define NWOUT (CH*INNER)     // 131072
__global__ void __launch_bounds__(256) convert_w_kernel(
    const float* __restrict__ wqkv, const float* __restrict__ wout)
{
    int i = blockIdx.x * 256 + threadIdx.x;
    if (i < NWQKV) {
        __nv_bfloat16 h, l;
        bf16_split(wqkv[i], h, l);
        g_w_hi[i] = h; g_w_lo[i] = l;
    } else {
        int j = i - NWQKV;
        __nv_bfloat16 h, l;
        bf16_split(wout[j], h, l);
        g_wo_hi[j] = h; g_wo_lo[j] = l;
    }
}

// ============================================================
// K0b: transpose x [b][c][hw] -> xt [b][hw][c], split bf16 hi/lo
// ============================================================
__global__ void __launch_bounds__(256) transpose_x_kernel(const float* __restrict__ x) {
    __shared__ float ts[32][33];
    const int b = blockIdx.z, c0 = blockIdx.y * 32, hw0 = blockIdx.x * 32;
    const int tx = threadIdx.x & 31, ty = threadIdx.x >> 5;
    const float* xb = x + ((size_t)b * CH + c0) * HW + hw0;
    #pragma unroll
    for (int i = 0; i < 4; i++) {
        int c = ty + i * 8;
        ts[c][tx] = xb[(size_t)c * HW + tx];
    }
    __syncthreads();
    size_t ob = ((size_t)b * HW + hw0) * CH + c0;
    #pragma unroll
    for (int i = 0; i < 4; i++) {
        int r = ty + i * 8;
        __nv_bfloat16 h, l;
        bf16_split(ts[tx][r], h, l);
        g_xt_hi[ob + (size_t)r * CH + tx] = h;
        g_xt_lo[ob + (size_t)r * CH + tx] = l;
    }
}

// ============================================================
// K1: qkv = w_qkv @ x via mma.sync bf16 3-pass split
// grid (12 m, 128 n, 8 b) — m fastest so concurrent CTAs share B via L2.
// ============================================================
#define K1P 72

extern __shared__ __nv_bfloat16 k1_sm[];

__global__ void __launch_bounds__(256, 2) qkv_mma_kernel() {
    __nv_bfloat16* As = k1_sm;
    __nv_bfloat16* Bs = k1_sm + 2 * 128 * K1P;

    const int tid = threadIdx.x;
    const int lane = tid & 31, warp = tid >> 5;
    const int wm = warp >> 2, wn = warp & 3;
    const int m0 = blockIdx.x * 128;
    const int n0 = blockIdx.y * 128;
    const int b  = blockIdx.z;

    float acc[4][4][4];
    #pragma unroll
    for (int i = 0; i < 4; i++)
        #pragma unroll
        for (int j = 0; j < 4; j++)
            #pragma unroll
            for (int q = 0; q < 4; q++) acc[i][j][q] = 0.f;

    for (int s = 0; s < 4; s++) {
        const int k0 = s * 64;
        #pragma unroll
        for (int sp = 0; sp < 2; sp++) {
            const __nv_bfloat16* src = sp ? g_w_lo : g_w_hi;
            __nv_bfloat16* dst = As + sp * 128 * K1P;
            #pragma unroll
            for (int it = 0; it < 4; it++) {
                int idx = tid + it * 256;
                int r = idx >> 3, c = (idx & 7) * 8;
                *reinterpret_cast<uint4*>(dst + r * K1P + c) =
                    *reinterpret_cast<const uint4*>(src + (size_t)(m0 + r) * CH + k0 + c);
            }
        }
        #pragma unroll
        for (int sp = 0; sp < 2; sp++) {
            const __nv_bfloat16* src = sp ? g_xt_lo : g_xt_hi;
            __nv_bfloat16* dst = Bs + sp * 128 * K1P;
            #pragma unroll
            for (int it = 0; it < 4; it++) {
                int idx = tid + it * 256;
                int r = idx >> 3, c = (idx & 7) * 8;
                *reinterpret_cast<uint4*>(dst + r * K1P + c) =
                    *reinterpret_cast<const uint4*>(src + ((size_t)b * HW + n0 + r) * CH + k0 + c);
            }
        }
        __syncthreads();

        #pragma unroll
        for (int p = 0; p < 3; p++) {
            const __nv_bfloat16* Ab = As + (p == 2 ? 128 * K1P : 0);
            const __nv_bfloat16* Bb = Bs + (p == 1 ? 128 * K1P : 0);
            #pragma unroll
            for (int ks = 0; ks < 4; ks++) {
                const int kk = ks * 16;
                uint32_t af[4][4], bf2[4][2];
                #pragma unroll
                for (int mt = 0; mt < 4; mt++) {
                    uint32_t a = smem_u32(Ab + (wm * 64 + mt * 16 + (lane & 15)) * K1P + kk + (lane >> 4) * 8);
                    ldsm4(a, af[mt][0], af[mt][1], af[mt][2], af[mt][3]);
                }
                #pragma unroll
                for (int np = 0; np < 2; np++) {
                    int nrow = wn * 32 + np * 16 + (lane & 7) + ((lane >> 4) & 1) * 8;
                    int kcol = kk + ((lane >> 3) & 1) * 8;
                    uint32_t a = smem_u32(Bb + nrow * K1P + kcol);
                    ldsm4(a, bf2[np*2][0], bf2[np*2][1], bf2[np*2+1][0], bf2[np*2+1][1]);
                }
                #pragma unroll
                for (int mt = 0; mt < 4; mt++)
                    #pragma unroll
                    for (int nt = 0; nt < 4; nt++)
                        mma16816(acc[mt][nt], af[mt], bf2[nt]);
            }
        }
        __syncthreads();
    }

    // epilogue -> q/k/v bf16 hi/lo
    const int g = lane >> 2, tig = lane & 3;
    #pragma unroll
    for (int mt = 0; mt < 4; mt++) {
        int mbase = m0 + wm * 64 + mt * 16;
        #pragma unroll
        for (int half = 0; half < 2; half++) {
            int m = mbase + g + half * 8;
            int kind = m >> 9, oo = m & 511;
            __nv_bfloat16 *dh, *dl;
            if (kind == 0)      { dh = g_q_hi; dl = g_q_lo; }
            else if (kind == 1) { dh = g_k_hi; dl = g_k_lo; }
            else                { dh = g_v_hi; dl = g_v_lo; }
            size_t rbase = ((size_t)b * INNER + oo) * HW + n0;
            #pragma unroll
            for (int nt = 0; nt < 4; nt++) {
                int col = wn * 32 + nt * 8 + tig * 2;
                __nv_bfloat16 h0, l0, h1, l1;
                bf16_split(acc[mt][nt][half*2],   h0, l0);
                bf16_split(acc[mt][nt][half*2+1], h1, l1);
                *reinterpret_cast<__nv_bfloat162*>(dh + rbase + col) = __nv_bfloat162(h0, h1);
                *reinterpret_cast<__nv_bfloat162*>(dl + rbase + col) = __nv_bfloat162(l0, l1);
            }
        }
    }
}

// ============================================================
// K2: axial attention via mma.sync bf16 3-pass split, cp.async
// double-buffered in both phases. grid (64, 2), 256 threads.
// ============================================================
#define PS 136   // bf16 row stride for P/V/mode-1 tiles (272 B)
#define QP 72    // bf16 row stride for mode-0 QK tiles (144 B)

// smem layout (bytes):
//  [0, 65536)          Ssm fp32 logits (phase 1) / V ping-pong buf0+buf1 (phase 2, 2x69632)
//  [65536, 212992)     phase-1 tile double buffer (2 x 73728)
//  [139264, 208896)    Ph/Pl (written at softmax, read in phase 2; inside dead tile buf region)
#define AT_T    65536
#define AT_TBUF 73728
#define AT_PH   139264
#define AT_PL   174080
#define AT_SMEM 212992

extern __shared__ char at_sm[];

// issue Q/K hi/lo tiles for k-slab s into tile buffer at byte offset tb
__device__ __forceinline__ void attn_issue_qk(
    const __nv_bfloat16* s0, const __nv_bfloat16* s1,
    const __nv_bfloat16* s2, const __nv_bfloat16* s3,
    int s, uint32_t tb, int tid, int mode)
{
    const __nv_bfloat16* srcs[4] = { s0, s1, s2, s3 };
    const int d = s >> 1, off = (s & 1) * 64;
    if (mode == 0) {
        #pragma unroll
        for (int t = 0; t < 4; t++) {
            const __nv_bfloat16* src = srcs[t] + (size_t)d * HW + off;
            uint32_t dstb = tb + t * 18432;
            #pragma unroll
            for (int it = 0; it < 4; it++) {
                int idx = tid + it * 256;
                int r = idx >> 3, c = idx & 7;
                cp16(dstb + r * 144 + c * 16, src + r * TOK + c * 8);
            }
        }
    } else {
        #pragma unroll
        for (int t = 0; t < 4; t++) {
            const __nv_bfloat16* src = srcs[t] + (size_t)d * HW + (size_t)off * TOK;
            uint32_t dstb = tb + t * 17408;
            #pragma unroll
            for (int it = 0; it < 4; it++) {
                int idx = tid + it * 256;
                int r = idx >> 4, c = idx & 15;
                cp16(dstb + r * 272 + c * 16, src + r * TOK + c * 8);
            }
        }
    }
    cp_commit();
}

// issue V hi/lo plane d into V buffer at byte offset vb
__device__ __forceinline__ void attn_issue_v(
    const __nv_bfloat16* vh, const __nv_bfloat16* vl, int d, uint32_t vb, int tid)
{
    #pragma unroll
    for (int sp = 0; sp < 2; sp++) {
        const __nv_bfloat16* src = (sp ? vl : vh) + (size_t)d * HW;
        uint32_t dstb = vb + sp * 34816;
        #pragma unroll
        for (int it = 0; it < 8; it++) {
            int idx = tid + it * 256;
            int r = idx >> 4, c = idx & 15;
            cp16(dstb + r * 272 + c * 16, src + r * TOK + c * 8);
        }
    }
    cp_commit();
}

__global__ void __launch_bounds__(256) attn_mma_kernel()
{
    float* Ssm = reinterpret_cast<float*>(at_sm);
    __nv_bfloat16* Ph = reinterpret_cast<__nv_bfloat16*>(at_sm + AT_PH);
    __nv_bfloat16* Pl = reinterpret_cast<__nv_bfloat16*>(at_sm + AT_PL);

    const int tid = threadIdx.x;
    const int lane = tid & 31, warp = tid >> 5;
    const int wm = warp >> 2, wn = warp & 3;
    const int g = lane >> 2, tig = lane & 3;
    const int bh = blockIdx.x, mode = blockIdx.y;
    const int b = bh >> 3, head = bh & 7;
    const uint32_t sbase = smem_u32(at_sm);

    const size_t pbase = ((size_t)b * INNER + head * DH) * HW;
    const __nv_bfloat16* __restrict__ qh = g_q_hi + pbase;
    const __nv_bfloat16* __restrict__ ql = g_q_lo + pbase;
    const __nv_bfloat16* __restrict__ kh = g_k_hi + pbase;
    const __nv_bfloat16* __restrict__ kl = g_k_lo + pbase;
    const __nv_bfloat16* __restrict__ vh = g_v_hi + pbase;
    const __nv_bfloat16* __restrict__ vl = g_v_lo + pbase;

    // ================= phase 1: S = Q K^T =================
    {
        float acc[4][4][4];
        #pragma unroll
        for (int i = 0; i < 4; i++)
            #pragma unroll
            for (int j = 0; j < 4; j++)
                #pragma unroll
                for (int q = 0; q < 4; q++) acc[i][j][q] = 0.f;

        attn_issue_qk(qh, ql, kh, kl, 0, sbase + AT_T, tid, mode);

        for (int s = 0; s < 128; s++) {
            const int buf = s & 1;
            if (s < 127) {
                attn_issue_qk(qh, ql, kh, kl, s + 1, sbase + AT_T + (buf ^ 1) * AT_TBUF, tid, mode);
                cp_wait<1>();
            } else {
                cp_wait<0>();
            }
            __syncthreads();

            const char* tbase = at_sm + AT_T + buf * AT_TBUF;

            #pragma unroll
            for (int p = 0; p < 3; p++) {
                const int ai = (p == 2) ? 1 : 0;       // Q lo on pass 2
                const int bi = (p == 1) ? 3 : 2;       // K lo on pass 1
                if (mode == 0) {
                    const __nv_bfloat16* Ab = reinterpret_cast<const __nv_bfloat16*>(tbase + ai * 18432);
                    const __nv_bfloat16* Bb = reinterpret_cast<const __nv_bfloat16*>(tbase + bi * 18432);
                    #pragma unroll
                    for (int ks = 0; ks < 4; ks++) {
                        const int kk = ks * 16;
                        uint32_t af[4][4], bf2[4][2];
                        #pragma unroll
                        for (int mt = 0; mt < 4; mt++) {
                            uint32_t a = smem_u32(Ab + (wm*64 + mt*16 + (lane & 15)) * QP + kk + (lane >> 4) * 8);
                            ldsm4(a, af[mt][0], af[mt][1], af[mt][2], af[mt][3]);
                        }
                        #pragma unroll
                        for (int np = 0; np < 2; np++) {
                            int nrow = wn*32 + np*16 + (lane & 7) + ((lane >> 4) & 1) * 8;
                            int kcol = kk + ((lane >> 3) & 1) * 8;
                            uint32_t a = smem_u32(Bb + nrow * QP + kcol);
                            ldsm4(a, bf2[np*2][0], bf2[np*2][1], bf2[np*2+1][0], bf2[np*2+1][1]);
                        }
                        #pragma unroll
                        for (int mt = 0; mt < 4; mt++)
                            #pragma unroll
                            for (int nt = 0; nt < 4; nt++)
                                mma16816(acc[mt][nt], af[mt], bf2[nt]);
                    }
                } else {
                    const __nv_bfloat16* Ab = reinterpret_cast<const __nv_bfloat16*>(tbase + ai * 17408);
                    const __nv_bfloat16* Bb = reinterpret_cast<const __nv_bfloat16*>(tbase + bi * 17408);
                    #pragma unroll
                    for (int ks = 0; ks < 4; ks++) {
                        const int kk = ks * 16;
                        uint32_t af[4][4], bf2[4][2];
                        #pragma unroll
                        for (int mt = 0; mt < 4; mt++) {   // trans-A from [k][m]
                            uint32_t a = smem_u32(Ab + (kk + (lane & 7) + ((lane >> 4) & 1) * 8) * PS
                                                     + wm*64 + mt*16 + ((lane >> 3) & 1) * 8);
                            ldsm4t(a, af[mt][0], af[mt][1], af[mt][2], af[mt][3]);
                        }
                        #pragma unroll
                        for (int np = 0; np < 2; np++) {   // trans-B from [k][n]
                            int krow = kk + (lane & 7) + ((lane >> 3) & 1) * 8;
                            int ncol = wn*32 + np*16 + ((lane >> 4) & 1) * 8;
                            uint32_t a = smem_u32(Bb + krow * PS + ncol);
                            ldsm4t(a, bf2[np*2][0], bf2[np*2][1], bf2[np*2+1][0], bf2[np*2+1][1]);
                        }
                        #pragma unroll
                        for (int mt = 0; mt < 4; mt++)
                            #pragma unroll
                            for (int nt = 0; nt < 4; nt++)
                                mma16816(acc[mt][nt], af[mt], bf2[nt]);
                    }
                }
            }
            __syncthreads();
        }

        // store logits S[j][i]
        #pragma unroll
        for (int mt = 0; mt < 4; mt++) {
            int i0 = wm*64 + mt*16 + g;
            #pragma unroll
            for (int nt = 0; nt < 4; nt++) {
                int j0 = wn*32 + nt*8 + tig*2;
                Ssm[j0 * TOK + i0]           = acc[mt][nt][0];
                Ssm[(j0+1) * TOK + i0]       = acc[mt][nt][1];
                Ssm[j0 * TOK + i0 + 8]       = acc[mt][nt][2];
                Ssm[(j0+1) * TOK + i0 + 8]   = acc[mt][nt][3];
            }
        }
    }
    __syncthreads();

    // ================= softmax over j, write P hi/lo =================
    if (tid < TOK) {
        const int i = tid;
        float mx = -1e30f;
        for (int j = 0; j < TOK; j++) mx = fmaxf(mx, Ssm[j * TOK + i]);
        float s = 0.f;
        for (int j = 0; j < TOK; j++) {
            float e = __expf((Ssm[j * TOK + i] - mx) * 0.125f);
            s += e;
            Ssm[j * TOK + i] = e;
        }
        float inv = 1.f / s;
        for (int j = 0; j < TOK; j++) {
            float pv = Ssm[j * TOK + i] * inv;
            __nv_bfloat16 h, l;
            bf16_split(pv, h, l);
            Ph[j * PS + i] = h;
            Pl[j * PS + i] = l;
        }
    }
    __syncthreads();   // Ssm dead after this; V buffers may overwrite it

    // ================= phase 2: O = P V =================
    float* outp = ((mode == 0) ? g_bufH : g_bufW) + pbase;

    attn_issue_v(vh, vl, 0, sbase, tid);

    for (int d = 0; d < DH; d++) {
        const int buf = d & 1;
        if (d < DH - 1) {
            attn_issue_v(vh, vl, d + 1, sbase + (buf ^ 1) * 69632, tid);
            cp_wait<1>();
        } else {
            cp_wait<0>();
        }
        __syncthreads();

        const __nv_bfloat16* Vh = reinterpret_cast<const __nv_bfloat16*>(at_sm + buf * 69632);
        const __nv_bfloat16* Vl = Vh + 128 * PS;

        float oacc[4][4][4];
        #pragma unroll
        for (int i = 0; i < 4; i++)
            #pragma unroll
            for (int j = 0; j < 4; j++)
                #pragma unroll
                for (int q = 0; q < 4; q++) oacc[i][j][q] = 0.f;

        #pragma unroll
        for (int p = 0; p < 3; p++) {
            if (mode == 0) {
                // A = P[i][j] (trans-A from Ps[j][i]); B = V[j][w] (trans-B)
                const __nv_bfloat16* Ab = (p == 2) ? Pl : Ph;
                const __nv_bfloat16* Bb = (p == 1) ? Vl : Vh;
                #pragma unroll
                for (int ks = 0; ks < 8; ks++) {
                    const int kk = ks * 16;
                    uint32_t af[4][4], bf2[4][2];
                    #pragma unroll
                    for (int mt = 0; mt < 4; mt++) {
                        uint32_t a = smem_u32(Ab + (kk + (lane & 7) + ((lane >> 4) & 1) * 8) * PS
                                                 + wm*64 + mt*16 + ((lane >> 3) & 1) * 8);
                        ldsm4t(a, af[mt][0], af[mt][1], af[mt][2], af[mt][3]);
                    }
                    #pragma unroll
                    for (int np = 0; np < 2; np++) {
                        int krow = kk + (lane & 7) + ((lane >> 3) & 1) * 8;
                        int ncol = wn*32 + np*16 + ((lane >> 4) & 1) * 8;
                        uint32_t a = smem_u32(Bb + krow * PS + ncol);
                        ldsm4t(a, bf2[np*2][0], bf2[np*2][1], bf2[np*2+1][0], bf2[np*2+1][1]);
                    }
                    #pragma unroll
                    for (int mt = 0; mt < 4; mt++)
                        #pragma unroll
                        for (int nt = 0; nt < 4; nt++)
                            mma16816(oacc[mt][nt], af[mt], bf2[nt]);
                }
            } else {
                // A = V[h][j] (plain rows); B = P[j][w] (trans-B)
                const __nv_bfloat16* Ab = (p == 2) ? Vl : Vh;
                const __nv_bfloat16* Bb = (p == 1) ? Pl : Ph;
                #pragma unroll
                for (int ks = 0; ks < 8; ks++) {
                    const int kk = ks * 16;
                    uint32_t af[4][4], bf2[4][2];
                    #pragma unroll
                    for (int mt = 0; mt < 4; mt++) {
                        uint32_t a = smem_u32(Ab + (wm*64 + mt*16 + (lane & 15)) * PS + kk + (lane >> 4) * 8);
                        ldsm4(a, af[mt][0], af[mt][1], af[mt][2], af[mt][3]);
                    }
                    #pragma unroll
                    for (int np = 0; np < 2; np++) {
                        int krow = kk + (lane & 7) + ((lane >> 3) & 1) * 8;
                        int ncol = wn*32 + np*16 + ((lane >> 4) & 1) * 8;
                        uint32_t a = smem_u32(Bb + krow * PS + ncol);
                        ldsm4t(a, bf2[np*2][0], bf2[np*2][1], bf2[np*2+1][0], bf2[np*2+1][1]);
                    }
                    #pragma unroll
                    for (int mt = 0; mt < 4; mt++)
                        #pragma unroll
                        for (int nt = 0; nt < 4; nt++)
                            mma16816(oacc[mt][nt], af[mt], bf2[nt]);
                }
            }
        }

        // epilogue: out_plane[m][n] -> outp[d][m][n] (coalesced, both modes)
        float* dstb = outp + (size_t)d * HW;
        #pragma unroll
        for (int mt = 0; mt < 4; mt++) {
            #pragma unroll
            for (int half = 0; half < 2; half++) {
                int m = wm*64 + mt*16 + g + half*8;
                float* rowp = dstb + (size_t)m * TOK;
                #pragma unroll
                for (int nt = 0; nt < 4; nt++) {
                    int col = wn*32 + nt*8 + tig*2;
                    *reinterpret_cast<float2*>(rowp + col) =
                        make_float2(oacc[mt][nt][half*2], oacc[mt][nt][half*2+1]);
                }
            }
        }
        __syncthreads();
    }
}

// ============================================================
// K3: out = w_out @ (0.5*(bufH+bufW)) + b_out + x  via mma.sync
// ============================================================
#define K3AP 72
#define K3BP 136

extern __shared__ __nv_bfloat16 k3_sm[];

__global__ void __launch_bounds__(256, 2) out_mma_kernel(
    const float* __restrict__ x, const float* __restrict__ bout, float* __restrict__ out)
{
    __nv_bfloat16* As = k3_sm;
    __nv_bfloat16* Bs = k3_sm + 2 * 128 * K3AP;

    const int tid = threadIdx.x;
    const int lane = tid & 31, warp = tid >> 5;
    const int wm = warp >> 2, wn = warp & 3;
    const int n0 = blockIdx.x * 128;
    const int m0 = blockIdx.y * 128;
    const int b  = blockIdx.z;

    float acc[4][4][4];
    #pragma unroll
    for (int i = 0; i < 4; i++)
        #pragma unroll
        for (int j = 0; j < 4; j++)
            #pragma unroll
            for (int q = 0; q < 4; q++) acc[i][j][q] = 0.f;

    for (int s = 0; s < 8; s++) {
        const int k0 = s * 64;
        #pragma unroll
        for (int sp = 0; sp < 2; sp++) {
            const __nv_bfloat16* src = sp ? g_wo_lo : g_wo_hi;
            __nv_bfloat16* dst = As + sp * 128 * K3AP;
            #pragma unroll
            for (int it = 0; it < 4; it++) {
                int idx = tid + it * 256;
                int r = idx >> 3, c = (idx & 7) * 8;
                *reinterpret_cast<uint4*>(dst + r * K3AP + c) =
                    *reinterpret_cast<const uint4*>(src + (size_t)(m0 + r) * INNER + k0 + c);
            }
        }
        {
            __nv_bfloat16* Bh = Bs;
            __nv_bfloat16* Bl = Bs + 64 * K3BP;
            #pragma unroll
            for (int it = 0; it < 8; it++) {
                int idx = tid + it * 256;
                int r = idx >> 5, c = (idx & 31) * 4;
                size_t gi = ((size_t)b * INNER + k0 + r) * HW + n0 + c;
                float4 hv = *reinterpret_cast<const float4*>(g_bufH + gi);
                float4 wv = *reinterpret_cast<const float4*>(g_bufW + gi);
                float s0 = 0.5f * (hv.x + wv.x), s1 = 0.5f * (hv.y + wv.y);
                float s2 = 0.5f * (hv.z + wv.z), s3 = 0.5f * (hv.w + wv.w);
                __nv_bfloat16 h0, l0, h1, l1, h2, l2, h3, l3;
                bf16_split(s0, h0, l0); bf16_split(s1, h1, l1);
                bf16_split(s2, h2, l2); bf16_split(s3, h3, l3);
                *reinterpret_cast<__nv_bfloat162*>(Bh + r * K3BP + c)     = __nv_bfloat162(h0, h1);
                *reinterpret_cast<__nv_bfloat162*>(Bh + r * K3BP + c + 2) = __nv_bfloat162(h2, h3);
                *reinterpret_cast<__nv_bfloat162*>(Bl + r * K3BP + c)     = __nv_bfloat162(l0, l1);
                *reinterpret_cast<__nv_bfloat162*>(Bl + r * K3BP + c + 2) = __nv_bfloat162(l2, l3);
            }
        }
        __syncthreads();

        #pragma unroll
        for (int p = 0; p < 3; p++) {
            const __nv_bfloat16* Ab = As + (p == 2 ? 128 * K3AP : 0);
            const __nv_bfloat16* Bb = Bs + (p == 1 ? 64 * K3BP : 0);
            #pragma unroll
            for (int ks = 0; ks < 4; ks++) {
                const int kk = ks * 16;
                uint32_t af[4][4], bf2[4][2];
                #pragma unroll
                for (int mt = 0; mt < 4; mt++) {
                    uint32_t a = smem_u32(Ab + (wm * 64 + mt * 16 + (lane & 15)) * K3AP + kk + (lane >> 4) * 8);
                    ldsm4(a, af[mt][0], af[mt][1], af[mt][2], af[mt][3]);
                }
                #pragma unroll
                for (int np = 0; np < 2; np++) {
                    int krow = kk + (lane & 7) + ((lane >> 3) & 1) * 8;
                    int ncol = wn * 32 + np * 16 + ((lane >> 4) & 1) * 8;
                    uint32_t a = smem_u32(Bb + krow * K3BP + ncol);
                    ldsm4t(a, bf2[np*2][0], bf2[np*2][1], bf2[np*2+1][0], bf2[np*2+1][1]);
                }
                #pragma unroll
                for (int mt = 0; mt < 4; mt++)
                    #pragma unroll
                    for (int nt = 0; nt < 4; nt++)
                        mma16816(acc[mt][nt], af[mt], bf2[nt]);
            }
        }
        __syncthreads();
    }

    const int g = lane >> 2, tig = lane & 3;
    #pragma unroll
    for (int mt = 0; mt < 4; mt++) {
        int mbase = m0 + wm * 64 + mt * 16;
        #pragma unroll
        for (int half = 0; half < 2; half++) {
            int m = mbase + g + half * 8;
            float bias = bout[m];
            size_t rbase = ((size_t)b * CH + m) * HW + n0;
            #pragma unroll
            for (int nt = 0; nt < 4; nt++) {
                int col = wn * 32 + nt * 8 + tig * 2;
                float2 xv = *reinterpret_cast<const float2*>(x + rbase + col);
                *reinterpret_cast<float2*>(out + rbase + col) =
                    make_float2(acc[mt][nt][half*2]   + bias + xv.x,
                                acc[mt][nt][half*2+1] + bias + xv.y);
            }
        }
    }
}

// ============================================================
extern "C" void kernel_launch(void* const* d_in, const int* in_sizes, int n_in,
                              void* d_out, int out_size) {
    (void)in_sizes; (void)n_in; (void)out_size;
    const float* x    = (const float*)d_in[0];
    const float* wqkv = (const float*)d_in[1];
    const float* wout = (const float*)d_in[2];
    const float* bout = (const float*)d_in[3];
    float* out = (float*)d_out;

    const int k1_bytes = 4 * 128 * K1P * (int)sizeof(__nv_bfloat16);                       // 73728
    const int k3_bytes = (2 * 128 * K3AP + 2 * 64 * K3BP) * (int)sizeof(__nv_bfloat16);    // 71680
    cudaFuncSetAttribute(qkv_mma_kernel,  cudaFuncAttributeMaxDynamicSharedMemorySize, k1_bytes);
    cudaFuncSetAttribute(attn_mma_kernel, cudaFuncAttributeMaxDynamicSharedMemorySize, AT_SMEM);
    cudaFuncSetAttribute(out_mma_kernel,  cudaFuncAttributeMaxDynamicSharedMemorySize, k3_bytes);

    convert_w_kernel<<<(NWQKV + NWOUT) / 256, 256>>>(wqkv, wout);
    transpose_x_kernel<<<dim3(HW / 32, CH / 32, BATCH), 256>>>(x);
    qkv_mma_kernel<<<dim3(1536 / 128, HW / 128, BATCH), 256, k1_bytes>>>();
    attn_mma_kernel<<<dim3(BATCH * HEADS, 2), 256, AT_SMEM>>>();
    out_mma_kernel<<<dim3(HW / 128, CH / 128, BATCH), 256, k3_bytes>>>(x, bout, out);
}

// round 8
// speedup vs baseline: 2.1190x; 1.1582x over previous
#include <cuda_runtime.h>
#include <cuda_bf16.h>
#include <cstdint>

#define BATCH 8
#define CH    256
#define HW    16384   // 128*128
#define TOK   128
#define HEADS 8
#define DH    64
#define INNER 512

// ---- scratch (device globals; no runtime allocation) ----
__device__ float g_bufH[(size_t)BATCH*INNER*HW];   // row-attn output  [b][o][hw]
__device__ float g_bufW[(size_t)BATCH*INNER*HW];   // col-attn output  [b][o][hw]
// bf16 split operands
__device__ __nv_bfloat16 g_w_hi[(size_t)3*INNER*CH];
__device__ __nv_bfloat16 g_w_lo[(size_t)3*INNER*CH];
__device__ __nv_bfloat16 g_wo_hi[(size_t)CH*INNER];
__device__ __nv_bfloat16 g_wo_lo[(size_t)CH*INNER];
__device__ __nv_bfloat16 g_xt_hi[(size_t)BATCH*HW*CH];  // [b][hw][c]
__device__ __nv_bfloat16 g_xt_lo[(size_t)BATCH*HW*CH];
// q/k/v bf16 hi/lo: [b][o=head*64+d][hw]
__device__ __nv_bfloat16 g_q_hi[(size_t)BATCH*INNER*HW];
__device__ __nv_bfloat16 g_q_lo[(size_t)BATCH*INNER*HW];
__device__ __nv_bfloat16 g_k_hi[(size_t)BATCH*INNER*HW];
__device__ __nv_bfloat16 g_k_lo[(size_t)BATCH*INNER*HW];
__device__ __nv_bfloat16 g_v_hi[(size_t)BATCH*INNER*HW];
__device__ __nv_bfloat16 g_v_lo[(size_t)BATCH*INNER*HW];

// ============================================================
// helpers
// ============================================================
__device__ __forceinline__ uint32_t smem_u32(const void* p) {
    uint32_t a;
    asm("{ .reg .u64 t; cvta.to.shared.u64 t, %1; cvt.u32.u64 %0, t; }" : "=r"(a) : "l"(p));
    return a;
}
__device__ __forceinline__ void ldsm4(uint32_t a, uint32_t& r0, uint32_t& r1, uint32_t& r2, uint32_t& r3) {
    asm volatile("ldmatrix.sync.aligned.m8n8.x4.shared.b16 {%0,%1,%2,%3}, [%4];"
                 : "=r"(r0),"=r"(r1),"=r"(r2),"=r"(r3) : "r"(a));
}
__device__ __forceinline__ void ldsm4t(uint32_t a, uint32_t& r0, uint32_t& r1, uint32_t& r2, uint32_t& r3) {
    asm volatile("ldmatrix.sync.aligned.m8n8.x4.trans.shared.b16 {%0,%1,%2,%3}, [%4];"
                 : "=r"(r0),"=r"(r1),"=r"(r2),"=r"(r3) : "r"(a));
}
__device__ __forceinline__ void mma16816(float* d, const uint32_t* a, const uint32_t* b) {
    asm volatile("mma.sync.aligned.m16n8k16.row.col.f32.bf16.bf16.f32 "
                 "{%0,%1,%2,%3}, {%4,%5,%6,%7}, {%8,%9}, {%0,%1,%2,%3};"
                 : "+f"(d[0]),"+f"(d[1]),"+f"(d[2]),"+f"(d[3])
                 : "r"(a[0]),"r"(a[1]),"r"(a[2]),"r"(a[3]), "r"(b[0]),"r"(b[1]));
}
__device__ __forceinline__ void bf16_split(float v, __nv_bfloat16& h, __nv_bfloat16& l) {
    h = __float2bfloat16(v);
    l = __float2bfloat16(v - __bfloat162float(h));
}
__device__ __forceinline__ void cp16(uint32_t dst, const void* src) {
    asm volatile("cp.async.cg.shared.global [%0], [%1], 16;" :: "r"(dst), "l"(src));
}
__device__ __forceinline__ void cp_commit() { asm volatile("cp.async.commit_group;" ::: "memory"); }
template<int N> __device__ __forceinline__ void cp_wait() {
    asm volatile("cp.async.wait_group %0;" :: "n"(N) : "memory");
}

// 3-pass split mma on preloaded fragments: acc += Ah*Bh + Ah*Bl + Al*Bh
__device__ __forceinline__ void mma_triple(
    float (&acc)[4][4][4],
    const uint32_t (&ah)[4][4], const uint32_t (&al)[4][4],
    const uint32_t (&bh)[4][2], const uint32_t (&bl)[4][2])
{
    #pragma unroll
    for (int mt = 0; mt < 4; mt++)
        #pragma unroll
        for (int nt = 0; nt < 4; nt++) {
            mma16816(acc[mt][nt], ah[mt], bh[nt]);
            mma16816(acc[mt][nt], ah[mt], bl[nt]);
            mma16816(acc[mt][nt], al[mt], bh[nt]);
        }
}

// ============================================================
// K0a: split w_qkv and w_out into bf16 hi/lo
// ============================================================
#define NWQKV (3*INNER*CH)   // 393216
#define NWOUT (CH*INNER)     // 131072
__global__ void __launch_bounds__(256) convert_w_kernel(
    const float* __restrict__ wqkv, const float* __restrict__ wout)
{
    int i = blockIdx.x * 256 + threadIdx.x;
    if (i < NWQKV) {
        __nv_bfloat16 h, l;
        bf16_split(wqkv[i], h, l);
        g_w_hi[i] = h; g_w_lo[i] = l;
    } else {
        int j = i - NWQKV;
        __nv_bfloat16 h, l;
        bf16_split(wout[j], h, l);
        g_wo_hi[j] = h; g_wo_lo[j] = l;
    }
}

// ============================================================
// K0b: transpose x [b][c][hw] -> xt [b][hw][c], split bf16 hi/lo
// ============================================================
__global__ void __launch_bounds__(256) transpose_x_kernel(const float* __restrict__ x) {
    __shared__ float ts[32][33];
    const int b = blockIdx.z, c0 = blockIdx.y * 32, hw0 = blockIdx.x * 32;
    const int tx = threadIdx.x & 31, ty = threadIdx.x >> 5;
    const float* xb = x + ((size_t)b * CH + c0) * HW + hw0;
    #pragma unroll
    for (int i = 0; i < 4; i++) {
        int c = ty + i * 8;
        ts[c][tx] = xb[(size_t)c * HW + tx];
    }
    __syncthreads();
    size_t ob = ((size_t)b * HW + hw0) * CH + c0;
    #pragma unroll
    for (int i = 0; i < 4; i++) {
        int r = ty + i * 8;
        __nv_bfloat16 h, l;
        bf16_split(ts[tx][r], h, l);
        g_xt_hi[ob + (size_t)r * CH + tx] = h;
        g_xt_lo[ob + (size_t)r * CH + tx] = l;
    }
}

// ============================================================
// K1: qkv = w_qkv @ x via mma.sync bf16 3-pass split
// cp.async double-buffered k-slabs. grid (12 m, 128 n, 8 b).
// stage layout: 4 regions of 18432 B: A_hi, A_lo, B_hi, B_lo; [128][K1P]
// ============================================================
#define K1P 72
#define K1_STAGE 73728

extern __shared__ char k1_sm[];

__device__ __forceinline__ void k1_issue(int m0, int n0, int b, int k0, uint32_t tb, int tid) {
    const __nv_bfloat16* srcs[4] = {
        g_w_hi + (size_t)m0 * CH + k0,
        g_w_lo + (size_t)m0 * CH + k0,
        g_xt_hi + ((size_t)b * HW + n0) * CH + k0,
        g_xt_lo + ((size_t)b * HW + n0) * CH + k0 };
    #pragma unroll
    for (int t = 0; t < 4; t++) {
        uint32_t dstb = tb + t * 18432;
        const __nv_bfloat16* src = srcs[t];
        #pragma unroll
        for (int it = 0; it < 4; it++) {
            int idx = tid + it * 256;
            int r = idx >> 3, c = idx & 7;
            cp16(dstb + r * 144 + c * 16, src + (size_t)r * CH + c * 8);
        }
    }
    cp_commit();
}

__global__ void __launch_bounds__(256) qkv_mma_kernel() {
    const int tid = threadIdx.x;
    const int lane = tid & 31, warp = tid >> 5;
    const int wm = warp >> 2, wn = warp & 3;
    const int m0 = blockIdx.x * 128;
    const int n0 = blockIdx.y * 128;
    const int b  = blockIdx.z;
    const uint32_t sbase = smem_u32(k1_sm);

    float acc[4][4][4];
    #pragma unroll
    for (int i = 0; i < 4; i++)
        #pragma unroll
        for (int j = 0; j < 4; j++)
            #pragma unroll
            for (int q = 0; q < 4; q++) acc[i][j][q] = 0.f;

    k1_issue(m0, n0, b, 0, sbase, tid);

    for (int s = 0; s < 4; s++) {
        const int buf = s & 1;
        if (s < 3) {
            k1_issue(m0, n0, b, (s + 1) * 64, sbase + (buf ^ 1) * K1_STAGE, tid);
            cp_wait<1>();
        } else {
            cp_wait<0>();
        }
        __syncthreads();

        const char* tb = k1_sm + buf * K1_STAGE;
        const __nv_bfloat16* Ah = reinterpret_cast<const __nv_bfloat16*>(tb);
        const __nv_bfloat16* Al = reinterpret_cast<const __nv_bfloat16*>(tb + 18432);
        const __nv_bfloat16* Bh = reinterpret_cast<const __nv_bfloat16*>(tb + 36864);
        const __nv_bfloat16* Bl = reinterpret_cast<const __nv_bfloat16*>(tb + 55296);

        #pragma unroll
        for (int ks = 0; ks < 4; ks++) {
            const int kk = ks * 16;
            uint32_t ah[4][4], al[4][4], bh[4][2], bl[4][2];
            #pragma unroll
            for (int mt = 0; mt < 4; mt++) {
                uint32_t off = (wm * 64 + mt * 16 + (lane & 15)) * K1P + kk + (lane >> 4) * 8;
                ldsm4(smem_u32(Ah + off), ah[mt][0], ah[mt][1], ah[mt][2], ah[mt][3]);
                ldsm4(smem_u32(Al + off), al[mt][0], al[mt][1], al[mt][2], al[mt][3]);
            }
            #pragma unroll
            for (int np = 0; np < 2; np++) {
                int nrow = wn * 32 + np * 16 + (lane & 7) + ((lane >> 4) & 1) * 8;
                int kcol = kk + ((lane >> 3) & 1) * 8;
                uint32_t off = nrow * K1P + kcol;
                ldsm4(smem_u32(Bh + off), bh[np*2][0], bh[np*2][1], bh[np*2+1][0], bh[np*2+1][1]);
                ldsm4(smem_u32(Bl + off), bl[np*2][0], bl[np*2][1], bl[np*2+1][0], bl[np*2+1][1]);
            }
            mma_triple(acc, ah, al, bh, bl);
        }
        __syncthreads();
    }

    // epilogue -> q/k/v bf16 hi/lo
    const int g = lane >> 2, tig = lane & 3;
    #pragma unroll
    for (int mt = 0; mt < 4; mt++) {
        int mbase = m0 + wm * 64 + mt * 16;
        #pragma unroll
        for (int half = 0; half < 2; half++) {
            int m = mbase + g + half * 8;
            int kind = m >> 9, oo = m & 511;
            __nv_bfloat16 *dh, *dl;
            if (kind == 0)      { dh = g_q_hi; dl = g_q_lo; }
            else if (kind == 1) { dh = g_k_hi; dl = g_k_lo; }
            else                { dh = g_v_hi; dl = g_v_lo; }
            size_t rbase = ((size_t)b * INNER + oo) * HW + n0;
            #pragma unroll
            for (int nt = 0; nt < 4; nt++) {
                int col = wn * 32 + nt * 8 + tig * 2;
                __nv_bfloat16 h0, l0, h1, l1;
                bf16_split(acc[mt][nt][half*2],   h0, l0);
                bf16_split(acc[mt][nt][half*2+1], h1, l1);
                *reinterpret_cast<__nv_bfloat162*>(dh + rbase + col) = __nv_bfloat162(h0, h1);
                *reinterpret_cast<__nv_bfloat162*>(dl + rbase + col) = __nv_bfloat162(l0, l1);
            }
        }
    }
}

// ============================================================
// K2: axial attention via mma.sync bf16 3-pass split, cp.async
// double-buffered in both phases. grid (64, 2), 256 threads.
// ============================================================
#define PS 136   // bf16 row stride for P/V/mode-1 tiles (272 B)
#define QP 72    // bf16 row stride for mode-0 QK tiles (144 B)

#define AT_T    65536
#define AT_TBUF 73728
#define AT_PH   139264
#define AT_PL   174080
#define AT_SMEM 212992

extern __shared__ char at_sm[];

__device__ __forceinline__ void attn_issue_qk(
    const __nv_bfloat16* s0, const __nv_bfloat16* s1,
    const __nv_bfloat16* s2, const __nv_bfloat16* s3,
    int s, uint32_t tb, int tid, int mode)
{
    const __nv_bfloat16* srcs[4] = { s0, s1, s2, s3 };
    const int d = s >> 1, off = (s & 1) * 64;
    if (mode == 0) {
        #pragma unroll
        for (int t = 0; t < 4; t++) {
            const __nv_bfloat16* src = srcs[t] + (size_t)d * HW + off;
            uint32_t dstb = tb + t * 18432;
            #pragma unroll
            for (int it = 0; it < 4; it++) {
                int idx = tid + it * 256;
                int r = idx >> 3, c = idx & 7;
                cp16(dstb + r * 144 + c * 16, src + r * TOK + c * 8);
            }
        }
    } else {
        #pragma unroll
        for (int t = 0; t < 4; t++) {
            const __nv_bfloat16* src = srcs[t] + (size_t)d * HW + (size_t)off * TOK;
            uint32_t dstb = tb + t * 17408;
            #pragma unroll
            for (int it = 0; it < 4; it++) {
                int idx = tid + it * 256;
                int r = idx >> 4, c = idx & 15;
                cp16(dstb + r * 272 + c * 16, src + r * TOK + c * 8);
            }
        }
    }
    cp_commit();
}

__device__ __forceinline__ void attn_issue_v(
    const __nv_bfloat16* vh, const __nv_bfloat16* vl, int d, uint32_t vb, int tid)
{
    #pragma unroll
    for (int sp = 0; sp < 2; sp++) {
        const __nv_bfloat16* src = (sp ? vl : vh) + (size_t)d * HW;
        uint32_t dstb = vb + sp * 34816;
        #pragma unroll
        for (int it = 0; it < 8; it++) {
            int idx = tid + it * 256;
            int r = idx >> 4, c = idx & 15;
            cp16(dstb + r * 272 + c * 16, src + r * TOK + c * 8);
        }
    }
    cp_commit();
}

__global__ void __launch_bounds__(256) attn_mma_kernel()
{
    float* Ssm = reinterpret_cast<float*>(at_sm);
    __nv_bfloat16* Ph = reinterpret_cast<__nv_bfloat16*>(at_sm + AT_PH);
    __nv_bfloat16* Pl = reinterpret_cast<__nv_bfloat16*>(at_sm + AT_PL);

    const int tid = threadIdx.x;
    const int lane = tid & 31, warp = tid >> 5;
    const int wm = warp >> 2, wn = warp & 3;
    const int g = lane >> 2, tig = lane & 3;
    const int bh2 = blockIdx.x, mode = blockIdx.y;
    const int b = bh2 >> 3, head = bh2 & 7;
    const uint32_t sbase = smem_u32(at_sm);

    const size_t pbase = ((size_t)b * INNER + head * DH) * HW;
    const __nv_bfloat16* __restrict__ qh = g_q_hi + pbase;
    const __nv_bfloat16* __restrict__ ql = g_q_lo + pbase;
    const __nv_bfloat16* __restrict__ kh = g_k_hi + pbase;
    const __nv_bfloat16* __restrict__ kl = g_k_lo + pbase;
    const __nv_bfloat16* __restrict__ vh = g_v_hi + pbase;
    const __nv_bfloat16* __restrict__ vl = g_v_lo + pbase;

    // ================= phase 1: S = Q K^T =================
    {
        float acc[4][4][4];
        #pragma unroll
        for (int i = 0; i < 4; i++)
            #pragma unroll
            for (int j = 0; j < 4; j++)
                #pragma unroll
                for (int q = 0; q < 4; q++) acc[i][j][q] = 0.f;

        attn_issue_qk(qh, ql, kh, kl, 0, sbase + AT_T, tid, mode);

        for (int s = 0; s < 128; s++) {
            const int buf = s & 1;
            if (s < 127) {
                attn_issue_qk(qh, ql, kh, kl, s + 1, sbase + AT_T + (buf ^ 1) * AT_TBUF, tid, mode);
                cp_wait<1>();
            } else {
                cp_wait<0>();
            }
            __syncthreads();

            const char* tbase = at_sm + AT_T + buf * AT_TBUF;

            if (mode == 0) {
                const __nv_bfloat16* Qh = reinterpret_cast<const __nv_bfloat16*>(tbase);
                const __nv_bfloat16* Ql = reinterpret_cast<const __nv_bfloat16*>(tbase + 18432);
                const __nv_bfloat16* Kh = reinterpret_cast<const __nv_bfloat16*>(tbase + 36864);
                const __nv_bfloat16* Kl = reinterpret_cast<const __nv_bfloat16*>(tbase + 55296);
                #pragma unroll
                for (int ks = 0; ks < 4; ks++) {
                    const int kk = ks * 16;
                    uint32_t ah[4][4], al[4][4], bh[4][2], bl[4][2];
                    #pragma unroll
                    for (int mt = 0; mt < 4; mt++) {
                        uint32_t off = (wm*64 + mt*16 + (lane & 15)) * QP + kk + (lane >> 4) * 8;
                        ldsm4(smem_u32(Qh + off), ah[mt][0], ah[mt][1], ah[mt][2], ah[mt][3]);
                        ldsm4(smem_u32(Ql + off), al[mt][0], al[mt][1], al[mt][2], al[mt][3]);
                    }
                    #pragma unroll
                    for (int np = 0; np < 2; np++) {
                        int nrow = wn*32 + np*16 + (lane & 7) + ((lane >> 4) & 1) * 8;
                        int kcol = kk + ((lane >> 3) & 1) * 8;
                        uint32_t off = nrow * QP + kcol;
                        ldsm4(smem_u32(Kh + off), bh[np*2][0], bh[np*2][1], bh[np*2+1][0], bh[np*2+1][1]);
                        ldsm4(smem_u32(Kl + off), bl[np*2][0], bl[np*2][1], bl[np*2+1][0], bl[np*2+1][1]);
                    }
                    mma_triple(acc, ah, al, bh, bl);
                }
            } else {
                const __nv_bfloat16* Qh = reinterpret_cast<const __nv_bfloat16*>(tbase);
                const __nv_bfloat16* Ql = reinterpret_cast<const __nv_bfloat16*>(tbase + 17408);
                const __nv_bfloat16* Kh = reinterpret_cast<const __nv_bfloat16*>(tbase + 34816);
                const __nv_bfloat16* Kl = reinterpret_cast<const __nv_bfloat16*>(tbase + 52224);
                #pragma unroll
                for (int ks = 0; ks < 4; ks++) {
                    const int kk = ks * 16;
                    uint32_t ah[4][4], al[4][4], bh[4][2], bl[4][2];
                    #pragma unroll
                    for (int mt = 0; mt < 4; mt++) {   // trans-A from [k][m]
                        uint32_t off = (kk + (lane & 7) + ((lane >> 4) & 1) * 8) * PS
                                       + wm*64 + mt*16 + ((lane >> 3) & 1) * 8;
                        ldsm4t(smem_u32(Qh + off), ah[mt][0], ah[mt][1], ah[mt][2], ah[mt][3]);
                        ldsm4t(smem_u32(Ql + off), al[mt][0], al[mt][1], al[mt][2], al[mt][3]);
                    }
                    #pragma unroll
                    for (int np = 0; np < 2; np++) {   // trans-B from [k][n]
                        int krow = kk + (lane & 7) + ((lane >> 3) & 1) * 8;
                        int ncol = wn*32 + np*16 + ((lane >> 4) & 1) * 8;
                        uint32_t off = krow * PS + ncol;
                        ldsm4t(smem_u32(Kh + off), bh[np*2][0], bh[np*2][1], bh[np*2+1][0], bh[np*2+1][1]);
                        ldsm4t(smem_u32(Kl + off), bl[np*2][0], bl[np*2][1], bl[np*2+1][0], bl[np*2+1][1]);
                    }
                    mma_triple(acc, ah, al, bh, bl);
                }
            }
            __syncthreads();
        }

        // store logits S[j][i]
        #pragma unroll
        for (int mt = 0; mt < 4; mt++) {
            int i0 = wm*64 + mt*16 + g;
            #pragma unroll
            for (int nt = 0; nt < 4; nt++) {
                int j0 = wn*32 + nt*8 + tig*2;
                Ssm[j0 * TOK + i0]           = acc[mt][nt][0];
                Ssm[(j0+1) * TOK + i0]       = acc[mt][nt][1];
                Ssm[j0 * TOK + i0 + 8]       = acc[mt][nt][2];
                Ssm[(j0+1) * TOK + i0 + 8]   = acc[mt][nt][3];
            }
        }
    }
    __syncthreads();

    // ================= softmax over j, write P hi/lo =================
    if (tid < TOK) {
        const int i = tid;
        float mx = -1e30f;
        for (int j = 0; j < TOK; j++) mx = fmaxf(mx, Ssm[j * TOK + i]);
        float s = 0.f;
        for (int j = 0; j < TOK; j++) {
            float e = __expf((Ssm[j * TOK + i] - mx) * 0.125f);
            s += e;
            Ssm[j * TOK + i] = e;
        }
        float inv = 1.f / s;
        for (int j = 0; j < TOK; j++) {
            float pv = Ssm[j * TOK + i] * inv;
            __nv_bfloat16 h, l;
            bf16_split(pv, h, l);
            Ph[j * PS + i] = h;
            Pl[j * PS + i] = l;
        }
    }
    __syncthreads();   // Ssm dead after this; V buffers may overwrite it

    // ================= phase 2: O = P V =================
    float* outp = ((mode == 0) ? g_bufH : g_bufW) + pbase;

    attn_issue_v(vh, vl, 0, sbase, tid);

    for (int d = 0; d < DH; d++) {
        const int buf = d & 1;
        if (d < DH - 1) {
            attn_issue_v(vh, vl, d + 1, sbase + (buf ^ 1) * 69632, tid);
            cp_wait<1>();
        } else {
            cp_wait<0>();
        }
        __syncthreads();

        const __nv_bfloat16* Vh = reinterpret_cast<const __nv_bfloat16*>(at_sm + buf * 69632);
        const __nv_bfloat16* Vl = Vh + 128 * PS;

        float oacc[4][4][4];
        #pragma unroll
        for (int i = 0; i < 4; i++)
            #pragma unroll
            for (int j = 0; j < 4; j++)
                #pragma unroll
                for (int q = 0; q < 4; q++) oacc[i][j][q] = 0.f;

        if (mode == 0) {
            // A = P (trans from Ps[j][i]); B = V (trans from Vs[j][w])
            #pragma unroll
            for (int ks = 0; ks < 8; ks++) {
                const int kk = ks * 16;
                uint32_t ah[4][4], al[4][4], bh[4][2], bl[4][2];
                #pragma unroll
                for (int mt = 0; mt < 4; mt++) {
                    uint32_t off = (kk + (lane & 7) + ((lane >> 4) & 1) * 8) * PS
                                   + wm*64 + mt*16 + ((lane >> 3) & 1) * 8;
                    ldsm4t(smem_u32(Ph + off), ah[mt][0], ah[mt][1], ah[mt][2], ah[mt][3]);
                    ldsm4t(smem_u32(Pl + off), al[mt][0], al[mt][1], al[mt][2], al[mt][3]);
                }
                #pragma unroll
                for (int np = 0; np < 2; np++) {
                    int krow = kk + (lane & 7) + ((lane >> 3) & 1) * 8;
                    int ncol = wn*32 + np*16 + ((lane >> 4) & 1) * 8;
                    uint32_t off = krow * PS + ncol;
                    ldsm4t(smem_u32(Vh + off), bh[np*2][0], bh[np*2][1], bh[np*2+1][0], bh[np*2+1][1]);
                    ldsm4t(smem_u32(Vl + off), bl[np*2][0], bl[np*2][1], bl[np*2+1][0], bl[np*2+1][1]);
                }
                mma_triple(oacc, ah, al, bh, bl);
            }
        } else {
            // A = V (plain rows); B = P (trans from Ps[j][i])
            #pragma unroll
            for (int ks = 0; ks < 8; ks++) {
                const int kk = ks * 16;
                uint32_t ah[4][4], al[4][4], bh[4][2], bl[4][2];
                #pragma unroll
                for (int mt = 0; mt < 4; mt++) {
                    uint32_t off = (wm*64 + mt*16 + (lane & 15)) * PS + kk + (lane >> 4) * 8;
                    ldsm4(smem_u32(Vh + off), ah[mt][0], ah[mt][1], ah[mt][2], ah[mt][3]);
                    ldsm4(smem_u32(Vl + off), al[mt][0], al[mt][1], al[mt][2], al[mt][3]);
                }
                #pragma unroll
                for (int np = 0; np < 2; np++) {
                    int krow = kk + (lane & 7) + ((lane >> 3) & 1) * 8;
                    int ncol = wn*32 + np*16 + ((lane >> 4) & 1) * 8;
                    uint32_t off = krow * PS + ncol;
                    ldsm4t(smem_u32(Ph + off), bh[np*2][0], bh[np*2][1], bh[np*2+1][0], bh[np*2+1][1]);
                    ldsm4t(smem_u32(Pl + off), bl[np*2][0], bl[np*2][1], bl[np*2+1][0], bl[np*2+1][1]);
                }
                mma_triple(oacc, ah, al, bh, bl);
            }
        }

        // epilogue: out_plane[m][n] -> outp[d][m][n] (coalesced, both modes)
        float* dstb = outp + (size_t)d * HW;
        #pragma unroll
        for (int mt = 0; mt < 4; mt++) {
            #pragma unroll
            for (int half = 0; half < 2; half++) {
                int m = wm*64 + mt*16 + g + half*8;
                float* rowp = dstb + (size_t)m * TOK;
                #pragma unroll
                for (int nt = 0; nt < 4; nt++) {
                    int col = wn*32 + nt*8 + tig*2;
                    *reinterpret_cast<float2*>(rowp + col) =
                        make_float2(oacc[mt][nt][half*2], oacc[mt][nt][half*2+1]);
                }
            }
        }
        __syncthreads();
    }
}

// ============================================================
// K3: out = w_out @ (0.5*(bufH+bufW)) + b_out + x  via mma.sync
// ============================================================
#define K3AP 72
#define K3BP 136

extern __shared__ __nv_bfloat16 k3_sm[];

__global__ void __launch_bounds__(256) out_mma_kernel(
    const float* __restrict__ x, const float* __restrict__ bout, float* __restrict__ out)
{
    __nv_bfloat16* As = k3_sm;
    __nv_bfloat16* Bs = k3_sm + 2 * 128 * K3AP;

    const int tid = threadIdx.x;
    const int lane = tid & 31, warp = tid >> 5;
    const int wm = warp >> 2, wn = warp & 3;
    const int n0 = blockIdx.x * 128;
    const int m0 = blockIdx.y * 128;
    const int b  = blockIdx.z;

    float acc[4][4][4];
    #pragma unroll
    for (int i = 0; i < 4; i++)
        #pragma unroll
        for (int j = 0; j < 4; j++)
            #pragma unroll
            for (int q = 0; q < 4; q++) acc[i][j][q] = 0.f;

    for (int s = 0; s < 8; s++) {
        const int k0 = s * 64;
        #pragma unroll
        for (int sp = 0; sp < 2; sp++) {
            const __nv_bfloat16* src = sp ? g_wo_lo : g_wo_hi;
            __nv_bfloat16* dst = As + sp * 128 * K3AP;
            #pragma unroll
            for (int it = 0; it < 4; it++) {
                int idx = tid + it * 256;
                int r = idx >> 3, c = (idx & 7) * 8;
                *reinterpret_cast<uint4*>(dst + r * K3AP + c) =
                    *reinterpret_cast<const uint4*>(src + (size_t)(m0 + r) * INNER + k0 + c);
            }
        }
        {
            __nv_bfloat16* Bh = Bs;
            __nv_bfloat16* Bl = Bs + 64 * K3BP;
            #pragma unroll
            for (int it = 0; it < 8; it++) {
                int idx = tid + it * 256;
                int r = idx >> 5, c = (idx & 31) * 4;
                size_t gi = ((size_t)b * INNER + k0 + r) * HW + n0 + c;
                float4 hv = *reinterpret_cast<const float4*>(g_bufH + gi);
                float4 wv = *reinterpret_cast<const float4*>(g_bufW + gi);
                float s0 = 0.5f * (hv.x + wv.x), s1 = 0.5f * (hv.y + wv.y);
                float s2 = 0.5f * (hv.z + wv.z), s3 = 0.5f * (hv.w + wv.w);
                __nv_bfloat16 h0, l0, h1, l1, h2, l2, h3, l3;
                bf16_split(s0, h0, l0); bf16_split(s1, h1, l1);
                bf16_split(s2, h2, l2); bf16_split(s3, h3, l3);
                *reinterpret_cast<__nv_bfloat162*>(Bh + r * K3BP + c)     = __nv_bfloat162(h0, h1);
                *reinterpret_cast<__nv_bfloat162*>(Bh + r * K3BP + c + 2) = __nv_bfloat162(h2, h3);
                *reinterpret_cast<__nv_bfloat162*>(Bl + r * K3BP + c)     = __nv_bfloat162(l0, l1);
                *reinterpret_cast<__nv_bfloat162*>(Bl + r * K3BP + c + 2) = __nv_bfloat162(l2, l3);
            }
        }
        __syncthreads();

        const __nv_bfloat16* Ah = As;
        const __nv_bfloat16* Al = As + 128 * K3AP;
        const __nv_bfloat16* Bhp = Bs;
        const __nv_bfloat16* Blp = Bs + 64 * K3BP;

        #pragma unroll
        for (int ks = 0; ks < 4; ks++) {
            const int kk = ks * 16;
            uint32_t ah[4][4], al[4][4], bh[4][2], bl[4][2];
            #pragma unroll
            for (int mt = 0; mt < 4; mt++) {
                uint32_t off = (wm * 64 + mt * 16 + (lane & 15)) * K3AP + kk + (lane >> 4) * 8;
                ldsm4(smem_u32(Ah + off), ah[mt][0], ah[mt][1], ah[mt][2], ah[mt][3]);
                ldsm4(smem_u32(Al + off), al[mt][0], al[mt][1], al[mt][2], al[mt][3]);
            }
            #pragma unroll
            for (int np = 0; np < 2; np++) {
                int krow = kk + (lane & 7) + ((lane >> 3) & 1) * 8;
                int ncol = wn * 32 + np * 16 + ((lane >> 4) & 1) * 8;
                uint32_t off = krow * K3BP + ncol;
                ldsm4t(smem_u32(Bhp + off), bh[np*2][0], bh[np*2][1], bh[np*2+1][0], bh[np*2+1][1]);
                ldsm4t(smem_u32(Blp + off), bl[np*2][0], bl[np*2][1], bl[np*2+1][0], bl[np*2+1][1]);
            }
            mma_triple(acc, ah, al, bh, bl);
        }
        __syncthreads();
    }

    const int g = lane >> 2, tig = lane & 3;
    #pragma unroll
    for (int mt = 0; mt < 4; mt++) {
        int mbase = m0 + wm * 64 + mt * 16;
        #pragma unroll
        for (int half = 0; half < 2; half++) {
            int m = mbase + g + half * 8;
            float bias = bout[m];
            size_t rbase = ((size_t)b * CH + m) * HW + n0;
            #pragma unroll
            for (int nt = 0; nt < 4; nt++) {
                int col = wn * 32 + nt * 8 + tig * 2;
                float2 xv = *reinterpret_cast<const float2*>(x + rbase + col);
                *reinterpret_cast<float2*>(out + rbase + col) =
                    make_float2(acc[mt][nt][half*2]   + bias + xv.x,
                                acc[mt][nt][half*2+1] + bias + xv.y);
            }
        }
    }
}

// ============================================================
extern "C" void kernel_launch(void* const* d_in, const int* in_sizes, int n_in,
                              void* d_out, int out_size) {
    (void)in_sizes; (void)n_in; (void)out_size;
    const float* x    = (const float*)d_in[0];
    const float* wqkv = (const float*)d_in[1];
    const float* wout = (const float*)d_in[2];
    const float* bout = (const float*)d_in[3];
    float* out = (float*)d_out;

    const int k1_bytes = 2 * K1_STAGE;                                                     // 147456
    const int k3_bytes = (2 * 128 * K3AP + 2 * 64 * K3BP) * (int)sizeof(__nv_bfloat16);    // 71680
    cudaFuncSetAttribute(qkv_mma_kernel,  cudaFuncAttributeMaxDynamicSharedMemorySize, k1_bytes);
    cudaFuncSetAttribute(attn_mma_kernel, cudaFuncAttributeMaxDynamicSharedMemorySize, AT_SMEM);
    cudaFuncSetAttribute(out_mma_kernel,  cudaFuncAttributeMaxDynamicSharedMemorySize, k3_bytes);

    convert_w_kernel<<<(NWQKV + NWOUT) / 256, 256>>>(wqkv, wout);
    transpose_x_kernel<<<dim3(HW / 32, CH / 32, BATCH), 256>>>(x);
    qkv_mma_kernel<<<dim3(1536 / 128, HW / 128, BATCH), 256, k1_bytes>>>();
    attn_mma_kernel<<<dim3(BATCH * HEADS, 2), 256, AT_SMEM>>>();
    out_mma_kernel<<<dim3(HW / 128, CH / 128, BATCH), 256, k3_bytes>>>(x, bout, out);
}